// round 7
// baseline (speedup 1.0000x reference)
#include <cuda_runtime.h>
#include <cuda_bf16.h>
#include <math.h>
#include <stdint.h>

#define N_TOK   2048
#define D_MODEL 2048
#define KV_D    512

// ---------------- scratch ---------------------------------------------------
__device__ __nv_bfloat16 g_xh[N_TOK * D_MODEL];
__device__ __nv_bfloat16 g_xl[N_TOK * D_MODEL];
__device__ __nv_bfloat16 g_ch[N_TOK * D_MODEL];
__device__ __nv_bfloat16 g_cl[N_TOK * D_MODEL];
__device__ __nv_bfloat16 g_Qh[N_TOK * D_MODEL];
__device__ __nv_bfloat16 g_Ql[N_TOK * D_MODEL];
__device__ __nv_bfloat16 g_Kh[N_TOK * KV_D];
__device__ __nv_bfloat16 g_Kl[N_TOK * KV_D];
__device__ __nv_bfloat16 g_Vth[KV_D * N_TOK];   // [kv][d][n]
__device__ __nv_bfloat16 g_Vtl[KV_D * N_TOK];
__device__ __nv_bfloat16 g_WqTh[D_MODEL * D_MODEL];
__device__ __nv_bfloat16 g_WqTl[D_MODEL * D_MODEL];
__device__ __nv_bfloat16 g_WkTh[KV_D * D_MODEL];
__device__ __nv_bfloat16 g_WkTl[KV_D * D_MODEL];
__device__ __nv_bfloat16 g_WvTh[KV_D * D_MODEL];
__device__ __nv_bfloat16 g_WvTl[KV_D * D_MODEL];
__device__ __nv_bfloat16 g_WoTh[D_MODEL * D_MODEL];
__device__ __nv_bfloat16 g_WoTl[D_MODEL * D_MODEL];
__device__ float2 g_rope[N_TOK * 64];

__device__ __forceinline__ uint32_t smem_u32(const void* p) {
    uint32_t a;
    asm("{ .reg .u64 t; cvta.to.shared.u64 t, %1; cvt.u32.u64 %0, t; }"
        : "=r"(a) : "l"(p));
    return a;
}

#define LDSM4(r, addr)                                                        \
    asm volatile("ldmatrix.sync.aligned.m8n8.x4.shared.b16 {%0,%1,%2,%3}, [%4];" \
                 : "=r"((r)[0]), "=r"((r)[1]), "=r"((r)[2]), "=r"((r)[3])     \
                 : "r"(addr))

#define MMA16816(d, a, b0, b1)                                                \
    asm volatile("mma.sync.aligned.m16n8k16.row.col.f32.bf16.bf16.f32 "       \
                 "{%0,%1,%2,%3}, {%4,%5,%6,%7}, {%8,%9}, {%0,%1,%2,%3};"      \
                 : "+f"((d)[0]), "+f"((d)[1]), "+f"((d)[2]), "+f"((d)[3])     \
                 : "r"((a)[0]), "r"((a)[1]), "r"((a)[2]), "r"((a)[3]),        \
                   "r"(b0), "r"(b1))

__device__ __forceinline__ void cpa16(uint32_t dst, const void* src) {
    asm volatile("cp.async.cg.shared.global [%0], [%1], 16;" :: "r"(dst), "l"(src));
}
#define CPA_COMMIT asm volatile("cp.async.commit_group;" ::: "memory")
#define CPA_WAIT(n) asm volatile("cp.async.wait_group %0;" :: "n"(n) : "memory")

__device__ __forceinline__ float fexp(float x) {
    float t = x * 1.4426950408889634f;
    t = fmaxf(t, -126.0f);
    float n = floorf(t);
    float f = t - n;
    float p = 1.5403530393283621e-4f;
    p = fmaf(p, f, 1.3333558146428443e-3f);
    p = fmaf(p, f, 9.6181291076284772e-3f);
    p = fmaf(p, f, 5.5504108664821580e-2f);
    p = fmaf(p, f, 2.4022650695910071e-1f);
    p = fmaf(p, f, 6.9314718055994531e-1f);
    p = fmaf(p, f, 1.0f);
    return __int_as_float(((int)n + 127) << 23) * p;
}

__device__ __forceinline__ void split2(float a, float b, __nv_bfloat162& h,
                                       __nv_bfloat162& l) {
    __nv_bfloat16 ha = __float2bfloat16(a), hb = __float2bfloat16(b);
    h = __nv_bfloat162(ha, hb);
    l = __nv_bfloat162(__float2bfloat16(a - __bfloat162float(ha)),
                       __float2bfloat16(b - __bfloat162float(hb)));
}

// ---------------------------------------------------------------------------
// Prep mega-kernel: act split | 4 weight transposes | rope table.
// ---------------------------------------------------------------------------
__global__ void __launch_bounds__(256) prep_all(
    const float* __restrict__ x, const float* __restrict__ Wq,
    const float* __restrict__ Wk, const float* __restrict__ Wv,
    const float* __restrict__ Wo,
    __nv_bfloat16* __restrict__ xh, __nv_bfloat16* __restrict__ xl,
    __nv_bfloat16* __restrict__ qth, __nv_bfloat16* __restrict__ qtl,
    __nv_bfloat16* __restrict__ kth, __nv_bfloat16* __restrict__ ktl,
    __nv_bfloat16* __restrict__ vth, __nv_bfloat16* __restrict__ vtl,
    __nv_bfloat16* __restrict__ oth, __nv_bfloat16* __restrict__ otl,
    float2* __restrict__ tab) {
    const int bid = blockIdx.x;
    const int tid = threadIdx.x;
    if (bid < 4096) {
        int i = (bid * 256 + tid) * 4;
        float4 v = *(const float4*)(x + i);
        __nv_bfloat162 h0, l0, h1, l1;
        split2(v.x, v.y, h0, l0);
        split2(v.z, v.w, h1, l1);
        __nv_bfloat162* ph = (__nv_bfloat162*)(xh + i);
        __nv_bfloat162* pl = (__nv_bfloat162*)(xl + i);
        ph[0] = h0; ph[1] = h1;
        pl[0] = l0; pl[1] = l1;
    } else if (bid < 14336) {
        __shared__ float t[32][33];
        int wb = bid - 4096;
        const float* in; __nv_bfloat16 *doh, *dol; int Ndim, nx, sid;
        if (wb < 4096)      { in = Wq; doh = qth; dol = qtl; Ndim = D_MODEL; nx = 64; sid = wb; }
        else if (wb < 5120) { in = Wk; doh = kth; dol = ktl; Ndim = KV_D;   nx = 16; sid = wb - 4096; }
        else if (wb < 6144) { in = Wv; doh = vth; dol = vtl; Ndim = KV_D;   nx = 16; sid = wb - 5120; }
        else                { in = Wo; doh = oth; dol = otl; Ndim = D_MODEL; nx = 64; sid = wb - 6144; }
        int n0 = (sid % nx) * 32, k0 = (sid / nx) * 32;
        int tx = tid & 31, ty = tid >> 5;
#pragma unroll
        for (int i = 0; i < 4; ++i)
            t[ty + 8 * i][tx] = in[(size_t)(k0 + ty + 8 * i) * Ndim + n0 + tx];
        __syncthreads();
#pragma unroll
        for (int i = 0; i < 4; ++i) {
            int nl = ty + 8 * i;
            float v = t[tx][nl];
            __nv_bfloat16 h = __float2bfloat16(v);
            size_t o = (size_t)(n0 + nl) * D_MODEL + k0 + tx;
            doh[o] = h;
            dol[o] = __float2bfloat16(v - __bfloat162float(h));
        }
    } else {
        int idx = (bid - 14336) * 256 + tid;
        int t = idx >> 6, i = idx & 63;
        double inv = exp(-9.210340371976184 * ((double)i / 64.0));
        double ang = (double)t * inv;
        double k = floor(ang * 0.15915494309189535);
        float r = (float)(ang - k * 6.283185307179586);
        float s, c;
        sincosf(r, &s, &c);
        tab[idx] = make_float2(c, s);
    }
}

// ---------------------------------------------------------------------------
// cp.async 3-stage bf16x3 GEMM core, split-pass MMA ordering.
// ---------------------------------------------------------------------------
#define GRS   80
#define GTB   (128 * GRS)
#define GSBUF (4 * GTB)
#define GSMEM (3 * GSBUF)

__device__ __forceinline__ void gemm_issue(
    uint32_t sbase, int slot, int c, int K, int tid,
    const __nv_bfloat16* pAh, const __nv_bfloat16* pAl,
    const __nv_bfloat16* pBh, const __nv_bfloat16* pBl) {
    const __nv_bfloat16* bases[4] = {pAh, pAl, pBh, pBl};
    uint32_t stage = sbase + slot * GSBUF;
#pragma unroll
    for (int t = 0; t < 4; ++t) {
#pragma unroll
        for (int i = 0; i < 2; ++i) {
            int idx = tid + i * 256;
            int r = idx >> 2, cc = idx & 3;
            cpa16(stage + t * GTB + r * GRS + cc * 16,
                  (const char*)bases[t] + ((size_t)r * K + c * 32) * 2 + cc * 16);
        }
    }
}

__device__ __forceinline__ void gemm_core_async(
    const __nv_bfloat16* __restrict__ pAh, const __nv_bfloat16* __restrict__ pAl,
    const __nv_bfloat16* __restrict__ pBh, const __nv_bfloat16* __restrict__ pBl,
    int K, uint32_t sbase, float acc[2][8][4]) {
    const int tid = threadIdx.x;
    const int lane = tid & 31;
    const int wid = tid >> 5;
    const int warp_m = wid & 3;
    const int warp_n = wid >> 2;
    const int q = lane >> 3;
    const int rowA = (lane & 7) + (q & 1) * 8;
    const int colA = (q >> 1) * 16;
    const int rowB = (lane & 7) + (q >> 1) * 8;
    const int colB = (q & 1) * 16;

    const int NC = K / 32;
    gemm_issue(sbase, 0, 0, K, tid, pAh, pAl, pBh, pBl);
    CPA_COMMIT;
    gemm_issue(sbase, 1, 1, K, tid, pAh, pAl, pBh, pBl);
    CPA_COMMIT;

    int slot = 0;
    for (int c = 0; c < NC; ++c) {
        CPA_WAIT(1);
        __syncthreads();
        if (c + 2 < NC) {
            int ns = slot + 2;
            if (ns >= 3) ns -= 3;
            gemm_issue(sbase, ns, c + 2, K, tid, pAh, pAl, pBh, pBl);
        }
        CPA_COMMIT;

        const uint32_t sb = sbase + slot * GSBUF;
#pragma unroll
        for (int ks = 0; ks < 2; ++ks) {
            uint32_t ah[2][4], al[2][4], bh[4][4], bl[4][4];
#pragma unroll
            for (int im = 0; im < 2; ++im) {
                uint32_t ra = sb + (warp_m * 32 + im * 16 + rowA) * GRS + ks * 32 + colA;
                LDSM4(ah[im], ra);
                LDSM4(al[im], ra + GTB);
            }
#pragma unroll
            for (int ib = 0; ib < 4; ++ib) {
                uint32_t rb = sb + 2 * GTB + (warp_n * 64 + ib * 16 + rowB) * GRS + ks * 32 + colB;
                LDSM4(bh[ib], rb);
                LDSM4(bl[ib], rb + GTB);
            }
            // split-pass ordering: 16 independent MMAs per pass
#pragma unroll
            for (int im = 0; im < 2; ++im)
#pragma unroll
                for (int j = 0; j < 8; ++j) {
                    const int f = j >> 1, h = (j & 1) * 2;
                    MMA16816(acc[im][j], ah[im], bh[f][h], bh[f][h + 1]);
                }
#pragma unroll
            for (int im = 0; im < 2; ++im)
#pragma unroll
                for (int j = 0; j < 8; ++j) {
                    const int f = j >> 1, h = (j & 1) * 2;
                    MMA16816(acc[im][j], ah[im], bl[f][h], bl[f][h + 1]);
                }
#pragma unroll
            for (int im = 0; im < 2; ++im)
#pragma unroll
                for (int j = 0; j < 8; ++j) {
                    const int f = j >> 1, h = (j & 1) * 2;
                    MMA16816(acc[im][j], al[im], bh[f][h], bh[f][h + 1]);
                }
        }
        if (++slot == 3) slot = 0;
    }
}

__device__ __forceinline__ void rope_split_store(
    const float2* __restrict__ tab, float v0, float v1, int row, int col, int N,
    __nv_bfloat16* __restrict__ oh, __nv_bfloat16* __restrict__ ol) {
    float2 cs = tab[row * 64 + ((col & 127) >> 1)];
    float oe = v0 * cs.x - v1 * cs.y;
    float oo = v0 * cs.y + v1 * cs.x;
    __nv_bfloat162 h, l;
    split2(oe, oo, h, l);
    *(__nv_bfloat162*)(oh + (size_t)row * N + col) = h;
    *(__nv_bfloat162*)(ol + (size_t)row * N + col) = l;
}

// ---- fused Q+K+V projection (384 blocks) ----------------------------------
__global__ void __launch_bounds__(256) hgemm_qkv(
    const __nv_bfloat16* __restrict__ Ah, const __nv_bfloat16* __restrict__ Al,
    const __nv_bfloat16* __restrict__ QBh, const __nv_bfloat16* __restrict__ QBl,
    const __nv_bfloat16* __restrict__ KBh, const __nv_bfloat16* __restrict__ KBl,
    const __nv_bfloat16* __restrict__ VBh, const __nv_bfloat16* __restrict__ VBl,
    __nv_bfloat16* __restrict__ qh, __nv_bfloat16* __restrict__ ql,
    __nv_bfloat16* __restrict__ kh, __nv_bfloat16* __restrict__ kl,
    __nv_bfloat16* __restrict__ vth, __nv_bfloat16* __restrict__ vtl,
    const float2* __restrict__ tab) {
    extern __shared__ char smem[];
    const uint32_t sbase = smem_u32(smem);
    const int bid = blockIdx.x;
    const int K = D_MODEL;
    int kind, m0, n0;
    const __nv_bfloat16 *Bh, *Bl;
    if (bid < 256)      { kind = 0; m0 = (bid >> 4) * 128; n0 = (bid & 15) * 128; Bh = QBh; Bl = QBl; }
    else if (bid < 320) { int s = bid - 256; kind = 1; m0 = (s >> 2) * 128; n0 = (s & 3) * 128; Bh = KBh; Bl = KBl; }
    else                { int s = bid - 320; kind = 2; m0 = (s >> 2) * 128; n0 = (s & 3) * 128; Bh = VBh; Bl = VBl; }

    float acc[2][8][4];
#pragma unroll
    for (int im = 0; im < 2; ++im)
#pragma unroll
        for (int j = 0; j < 8; ++j)
#pragma unroll
            for (int e = 0; e < 4; ++e) acc[im][j][e] = 0.f;
    gemm_core_async(Ah + (size_t)m0 * K, Al + (size_t)m0 * K,
                    Bh + (size_t)n0 * K, Bl + (size_t)n0 * K, K, sbase, acc);

    const int tid = threadIdx.x;
    const int lane = tid & 31, wid = tid >> 5;
    const int q4 = lane >> 2, l4 = lane & 3;
    if (kind == 0 || kind == 1) {
        const int N = (kind == 0) ? D_MODEL : KV_D;
        __nv_bfloat16* oh = (kind == 0) ? qh : kh;
        __nv_bfloat16* ol = (kind == 0) ? ql : kl;
#pragma unroll
        for (int im = 0; im < 2; ++im)
#pragma unroll
            for (int j = 0; j < 8; ++j) {
                int row = m0 + (wid & 3) * 32 + im * 16 + q4;
                int col = n0 + (wid >> 2) * 64 + j * 8 + l4 * 2;
                rope_split_store(tab, acc[im][j][0], acc[im][j][1], row, col, N, oh, ol);
                rope_split_store(tab, acc[im][j][2], acc[im][j][3], row + 8, col, N, oh, ol);
            }
    } else {
        __syncthreads();
        float* tS = (float*)smem;  // [128 d][132]
#pragma unroll
        for (int im = 0; im < 2; ++im)
#pragma unroll
            for (int j = 0; j < 8; ++j) {
                int r = (wid & 3) * 32 + im * 16 + q4;
                int cl = (wid >> 2) * 64 + j * 8 + l4 * 2;
                tS[cl * 132 + r] = acc[im][j][0];
                tS[(cl + 1) * 132 + r] = acc[im][j][1];
                tS[cl * 132 + r + 8] = acc[im][j][2];
                tS[(cl + 1) * 132 + r + 8] = acc[im][j][3];
            }
        __syncthreads();
        const int dkv = n0 >> 7;
        const int d = tid >> 1, half = (tid & 1) * 64;
        size_t dst = (size_t)dkv * 128 * N_TOK + (size_t)d * N_TOK + m0 + half;
#pragma unroll
        for (int k = 0; k < 64; k += 2) {
            __nv_bfloat162 h, l;
            split2(tS[d * 132 + half + k], tS[d * 132 + half + k + 1], h, l);
            *(__nv_bfloat162*)(vth + dst + k) = h;
            *(__nv_bfloat162*)(vtl + dst + k) = l;
        }
    }
}

// ---- output projection ----------------------------------------------------
__global__ void __launch_bounds__(256) hgemm_o(
    const __nv_bfloat16* __restrict__ Ah, const __nv_bfloat16* __restrict__ Al,
    const __nv_bfloat16* __restrict__ Bh, const __nv_bfloat16* __restrict__ Bl,
    float* __restrict__ C) {
    extern __shared__ char smem[];
    const uint32_t sbase = smem_u32(smem);
    const int m0 = blockIdx.y * 128, n0 = blockIdx.x * 128;
    const int K = D_MODEL, N = D_MODEL;
    float acc[2][8][4];
#pragma unroll
    for (int im = 0; im < 2; ++im)
#pragma unroll
        for (int j = 0; j < 8; ++j)
#pragma unroll
            for (int e = 0; e < 4; ++e) acc[im][j][e] = 0.f;
    gemm_core_async(Ah + (size_t)m0 * K, Al + (size_t)m0 * K,
                    Bh + (size_t)n0 * K, Bl + (size_t)n0 * K, K, sbase, acc);
    const int lane = threadIdx.x & 31, wid = threadIdx.x >> 5;
#pragma unroll
    for (int im = 0; im < 2; ++im)
#pragma unroll
        for (int j = 0; j < 8; ++j) {
            int row = m0 + (wid & 3) * 32 + im * 16 + (lane >> 2);
            int col = n0 + (wid >> 2) * 64 + j * 8 + (lane & 3) * 2;
            *(float2*)(C + (size_t)row * N + col) = make_float2(acc[im][j][0], acc[im][j][1]);
            *(float2*)(C + (size_t)(row + 8) * N + col) = make_float2(acc[im][j][2], acc[im][j][3]);
        }
}

// ---------------------------------------------------------------------------
// Flash attention: Q resident, K double-buffered cp.async, V pipelined,
// split-pass MMA ordering (pairwise interleave).
// ---------------------------------------------------------------------------
#define RSQ 272
#define RSV 144
#define OQH 0
#define OQL 34816
#define OKST 69632
#define OVH 139264
#define OVL 157696
#define OPH 176128
#define OPL 194560
#define FSMEM 212992

__global__ void __launch_bounds__(256, 1) flash_mma(
    const __nv_bfloat16* __restrict__ Qh, const __nv_bfloat16* __restrict__ Ql,
    const __nv_bfloat16* __restrict__ Kh, const __nv_bfloat16* __restrict__ Kl,
    const __nv_bfloat16* __restrict__ Vth, const __nv_bfloat16* __restrict__ Vtl,
    __nv_bfloat16* __restrict__ ch, __nv_bfloat16* __restrict__ cl) {
    const int qt = gridDim.x - 1 - blockIdx.x;
    const int h  = blockIdx.y;
    const int g  = h >> 2, kv = h & 3;
    const int qcol0 = g * 512 + kv * 128;
    const int kcol0 = kv * 128;
    const int ocol0 = (kv * 4 + g) * 128;
    const __nv_bfloat16* vh = Vth + (size_t)kv * 128 * N_TOK;
    const __nv_bfloat16* vl = Vtl + (size_t)kv * 128 * N_TOK;

    extern __shared__ char smem[];
    const uint32_t sbase = smem_u32(smem);

    const int tid = threadIdx.x;
    const int lane = tid & 31;
    const int warp_m = tid >> 5;
    const int q4 = lane >> 2, l4 = lane & 3;
    const int qq = lane >> 3;
    const int rowA = (lane & 7) + (qq & 1) * 8;
    const int colA = (qq >> 1) * 16;
    const int rowB = (lane & 7) + (qq >> 1) * 8;
    const int colB = (qq & 1) * 16;
    const float SCALE = 0.08838834764831845f;

#pragma unroll
    for (int i = 0; i < 8; ++i) {
        int idx = tid + i * 256;
        int r = idx >> 4, c = idx & 15;
        size_t go = (size_t)(qt * 128 + r) * D_MODEL + qcol0 + c * 8;
        *(uint4*)(smem + OQH + r * RSQ + c * 16) = *(const uint4*)(Qh + go);
        *(uint4*)(smem + OQL + r * RSQ + c * 16) = *(const uint4*)(Ql + go);
    }

    {
#pragma unroll
        for (int i = 0; i < 8; ++i) {
            int idx = tid + i * 256;
            int half = i >> 2;
            int li = idx & 1023;
            int r = li >> 4, c = li & 15;
            const __nv_bfloat16* src = half ? Kl : Kh;
            cpa16(sbase + OKST + half * 17408 + r * RSQ + c * 16,
                  src + (size_t)r * KV_D + kcol0 + c * 8);
        }
        CPA_COMMIT;
    }

    float o[16][4];
#pragma unroll
    for (int f = 0; f < 16; ++f)
#pragma unroll
        for (int e = 0; e < 4; ++e) o[f][e] = 0.f;
    float m0 = -1e30f, m1 = -1e30f, l0 = 0.f, l1 = 0.f;

    const int nkt = 2 * qt + 2;
    for (int kt = 0; kt < nkt; ++kt) {
        __syncthreads();

#pragma unroll
        for (int i = 0; i < 8; ++i) {
            int idx = tid + i * 256;
            int half = i >> 2;
            int li = idx & 1023;
            int r = li >> 3, c = li & 7;
            const __nv_bfloat16* src = half ? vl : vh;
            cpa16(sbase + (half ? OVL : OVH) + r * RSV + c * 16,
                  src + (size_t)r * N_TOK + kt * 64 + c * 8);
        }
        if (kt + 1 < nkt) {
            uint32_t kst = sbase + OKST + ((kt + 1) & 1) * 34816;
#pragma unroll
            for (int i = 0; i < 8; ++i) {
                int idx = tid + i * 256;
                int half = i >> 2;
                int li = idx & 1023;
                int r = li >> 4, c = li & 15;
                const __nv_bfloat16* src = half ? Kl : Kh;
                cpa16(kst + half * 17408 + r * RSQ + c * 16,
                      src + (size_t)((kt + 1) * 64 + r) * KV_D + kcol0 + c * 8);
            }
        }
        CPA_COMMIT;

        CPA_WAIT(1);
        __syncthreads();

        const int rbase = qt * 128 + warp_m * 16;
        const bool active = (kt * 64) <= (rbase + 15);
        const uint32_t kst = sbase + OKST + (kt & 1) * 34816;

        if (active) {
            float sacc[8][4];
#pragma unroll
            for (int j = 0; j < 8; ++j)
#pragma unroll
                for (int e = 0; e < 4; ++e) sacc[j][e] = 0.f;
#pragma unroll
            for (int ks = 0; ks < 8; ++ks) {
                uint32_t ah[4], al[4];
                uint32_t ra = sbase + OQH + (warp_m * 16 + rowA) * RSQ + ks * 32 + colA;
                LDSM4(ah, ra);
                LDSM4(al, ra + (OQL - OQH));
#pragma unroll
                for (int p = 0; p < 2; ++p) {       // key n-group pairs
                    uint32_t bh[2][4], bl[2][4];
#pragma unroll
                    for (int u = 0; u < 2; ++u) {
                        uint32_t rb = kst + ((p * 2 + u) * 16 + rowB) * RSQ + ks * 32 + colB;
                        LDSM4(bh[u], rb);
                        LDSM4(bl[u], rb + 17408);
                    }
                    // pass hh (4 independent), hl, lh
#pragma unroll
                    for (int u = 0; u < 2; ++u)
#pragma unroll
                        for (int half = 0; half < 2; ++half)
                            MMA16816(sacc[(p * 2 + u) * 2 + half], ah, bh[u][half * 2], bh[u][half * 2 + 1]);
#pragma unroll
                    for (int u = 0; u < 2; ++u)
#pragma unroll
                        for (int half = 0; half < 2; ++half)
                            MMA16816(sacc[(p * 2 + u) * 2 + half], ah, bl[u][half * 2], bl[u][half * 2 + 1]);
#pragma unroll
                    for (int u = 0; u < 2; ++u)
#pragma unroll
                        for (int half = 0; half < 2; ++half)
                            MMA16816(sacc[(p * 2 + u) * 2 + half], al, bh[u][half * 2], bh[u][half * 2 + 1]);
                }
            }
            const bool needMask = (kt * 64 + 63) > rbase;
#pragma unroll
            for (int j = 0; j < 8; ++j)
#pragma unroll
                for (int e = 0; e < 4; ++e) {
                    float v = sacc[j][e] * SCALE;
                    if (needMask) {
                        int rg = rbase + q4 + (e >> 1) * 8;
                        int kg = kt * 64 + j * 8 + l4 * 2 + (e & 1);
                        if (kg > rg) v = -1e30f;
                    }
                    sacc[j][e] = v;
                }
            float mx0 = -1e30f, mx1 = -1e30f;
#pragma unroll
            for (int j = 0; j < 8; ++j) {
                mx0 = fmaxf(mx0, fmaxf(sacc[j][0], sacc[j][1]));
                mx1 = fmaxf(mx1, fmaxf(sacc[j][2], sacc[j][3]));
            }
            mx0 = fmaxf(mx0, __shfl_xor_sync(0xffffffffu, mx0, 1));
            mx0 = fmaxf(mx0, __shfl_xor_sync(0xffffffffu, mx0, 2));
            mx1 = fmaxf(mx1, __shfl_xor_sync(0xffffffffu, mx1, 1));
            mx1 = fmaxf(mx1, __shfl_xor_sync(0xffffffffu, mx1, 2));
            float nm0 = fmaxf(m0, mx0), nm1 = fmaxf(m1, mx1);
            float corr0 = fexp(m0 - nm0), corr1 = fexp(m1 - nm1);
            m0 = nm0; m1 = nm1;
            float s0 = 0.f, s1 = 0.f;
            uint32_t prow0 = sbase + OPH + (warp_m * 16 + q4) * RSV + l4 * 4;
            uint32_t prow1 = prow0 + 8 * RSV;
#pragma unroll
            for (int j = 0; j < 8; ++j) {
                float p00 = fexp(sacc[j][0] - m0);
                float p01 = fexp(sacc[j][1] - m0);
                float p10 = fexp(sacc[j][2] - m1);
                float p11 = fexp(sacc[j][3] - m1);
                s0 += p00 + p01; s1 += p10 + p11;
                __nv_bfloat162 hp0, lp0, hp1, lp1;
                split2(p00, p01, hp0, lp0);
                split2(p10, p11, hp1, lp1);
                asm volatile("st.shared.b32 [%0], %1;" :: "r"(prow0 + j * 16), "r"(*(uint32_t*)&hp0));
                asm volatile("st.shared.b32 [%0], %1;" :: "r"(prow1 + j * 16), "r"(*(uint32_t*)&hp1));
                asm volatile("st.shared.b32 [%0], %1;" :: "r"(prow0 + (OPL - OPH) + j * 16), "r"(*(uint32_t*)&lp0));
                asm volatile("st.shared.b32 [%0], %1;" :: "r"(prow1 + (OPL - OPH) + j * 16), "r"(*(uint32_t*)&lp1));
            }
            s0 += __shfl_xor_sync(0xffffffffu, s0, 1);
            s0 += __shfl_xor_sync(0xffffffffu, s0, 2);
            s1 += __shfl_xor_sync(0xffffffffu, s1, 1);
            s1 += __shfl_xor_sync(0xffffffffu, s1, 2);
            l0 = l0 * corr0 + s0;
            l1 = l1 * corr1 + s1;
#pragma unroll
            for (int f = 0; f < 16; ++f) {
                o[f][0] *= corr0; o[f][1] *= corr0;
                o[f][2] *= corr1; o[f][3] *= corr1;
            }
        }

        CPA_WAIT(0);
        __syncthreads();

        if (active) {
#pragma unroll
            for (int ks = 0; ks < 4; ++ks) {
                uint32_t pa[4], pl_[4];
                uint32_t raddr = sbase + OPH + (warp_m * 16 + rowA) * RSV + ks * 32 + colA;
                LDSM4(pa, raddr);
                LDSM4(pl_, raddr + (OPL - OPH));
#pragma unroll
                for (int p = 0; p < 4; ++p) {       // d n-group pairs
                    uint32_t vb[2][4], vbl[2][4];
#pragma unroll
                    for (int u = 0; u < 2; ++u) {
                        uint32_t b0 = sbase + OVH + ((p * 2 + u) * 16 + rowB) * RSV + ks * 32 + colB;
                        LDSM4(vb[u], b0);
                        LDSM4(vbl[u], b0 + (OVL - OVH));
                    }
#pragma unroll
                    for (int u = 0; u < 2; ++u)
#pragma unroll
                        for (int half = 0; half < 2; ++half)
                            MMA16816(o[(p * 2 + u) * 2 + half], pa, vb[u][half * 2], vb[u][half * 2 + 1]);
#pragma unroll
                    for (int u = 0; u < 2; ++u)
#pragma unroll
                        for (int half = 0; half < 2; ++half)
                            MMA16816(o[(p * 2 + u) * 2 + half], pa, vbl[u][half * 2], vbl[u][half * 2 + 1]);
#pragma unroll
                    for (int u = 0; u < 2; ++u)
#pragma unroll
                        for (int half = 0; half < 2; ++half)
                            MMA16816(o[(p * 2 + u) * 2 + half], pl_, vb[u][half * 2], vb[u][half * 2 + 1]);
                }
            }
        }
    }

    float i0 = 1.f / l0, i1 = 1.f / l1;
    int row0 = qt * 128 + warp_m * 16 + q4;
#pragma unroll
    for (int f = 0; f < 16; ++f) {
        int col = ocol0 + f * 8 + l4 * 2;
        __nv_bfloat162 h0, l0v, h1, l1v;
        split2(o[f][0] * i0, o[f][1] * i0, h0, l0v);
        split2(o[f][2] * i1, o[f][3] * i1, h1, l1v);
        *(__nv_bfloat162*)(ch + (size_t)row0 * D_MODEL + col) = h0;
        *(__nv_bfloat162*)(ch + (size_t)(row0 + 8) * D_MODEL + col) = h1;
        *(__nv_bfloat162*)(cl + (size_t)row0 * D_MODEL + col) = l0v;
        *(__nv_bfloat162*)(cl + (size_t)(row0 + 8) * D_MODEL + col) = l1v;
    }
}

// ---------------------------------------------------------------------------
extern "C" void kernel_launch(void* const* d_in, const int* in_sizes, int n_in,
                              void* d_out, int out_size) {
    const float* x  = (const float*)d_in[0];
    const float* Wq = (const float*)d_in[1];
    const float* Wk = (const float*)d_in[2];
    const float* Wv = (const float*)d_in[3];
    const float* Wo = (const float*)d_in[4];
    float* out = (float*)d_out;

    __nv_bfloat16 *xh, *xl, *ch, *cl, *qh, *ql, *kh, *kl, *vth, *vtl;
    __nv_bfloat16 *qth, *qtl, *kth, *ktl, *vwh, *vwl, *oth, *otl;
    float2* tab;
    cudaGetSymbolAddress((void**)&xh, g_xh);   cudaGetSymbolAddress((void**)&xl, g_xl);
    cudaGetSymbolAddress((void**)&ch, g_ch);   cudaGetSymbolAddress((void**)&cl, g_cl);
    cudaGetSymbolAddress((void**)&qh, g_Qh);   cudaGetSymbolAddress((void**)&ql, g_Ql);
    cudaGetSymbolAddress((void**)&kh, g_Kh);   cudaGetSymbolAddress((void**)&kl, g_Kl);
    cudaGetSymbolAddress((void**)&vth, g_Vth); cudaGetSymbolAddress((void**)&vtl, g_Vtl);
    cudaGetSymbolAddress((void**)&qth, g_WqTh); cudaGetSymbolAddress((void**)&qtl, g_WqTl);
    cudaGetSymbolAddress((void**)&kth, g_WkTh); cudaGetSymbolAddress((void**)&ktl, g_WkTl);
    cudaGetSymbolAddress((void**)&vwh, g_WvTh); cudaGetSymbolAddress((void**)&vwl, g_WvTl);
    cudaGetSymbolAddress((void**)&oth, g_WoTh); cudaGetSymbolAddress((void**)&otl, g_WoTl);
    cudaGetSymbolAddress((void**)&tab, g_rope);

    cudaFuncSetAttribute(hgemm_qkv, cudaFuncAttributeMaxDynamicSharedMemorySize, GSMEM);
    cudaFuncSetAttribute(hgemm_o,   cudaFuncAttributeMaxDynamicSharedMemorySize, GSMEM);
    cudaFuncSetAttribute(flash_mma, cudaFuncAttributeMaxDynamicSharedMemorySize, FSMEM);

    prep_all<<<14848, 256>>>(x, Wq, Wk, Wv, Wo, xh, xl, qth, qtl, kth, ktl,
                             vwh, vwl, oth, otl, tab);
    hgemm_qkv<<<384, 256, GSMEM>>>(xh, xl, qth, qtl, kth, ktl, vwh, vwl,
                                   qh, ql, kh, kl, vth, vtl, tab);
    flash_mma<<<dim3(N_TOK / 128, 16), 256, FSMEM>>>(qh, ql, kh, kl, vth, vtl, ch, cl);
    hgemm_o<<<dim3(16, 16), 256, GSMEM>>>(ch, cl, oth, otl, out);

    (void)in_sizes; (void)n_in; (void)out_size;
}

// round 9
// speedup vs baseline: 1.4118x; 1.4118x over previous
#include <cuda_runtime.h>
#include <cuda_fp16.h>
#include <math.h>
#include <stdint.h>

#define N_TOK   2048
#define D_MODEL 2048
#define KV_D    512

// ---------------- scratch ---------------------------------------------------
__device__ __half g_xs[N_TOK * D_MODEL];          // x, single fp16
__device__ __half g_cs[N_TOK * D_MODEL];          // ctx, single fp16
__device__ __half g_Qs[N_TOK * D_MODEL];          // Q (roped), single fp16
__device__ __half g_Kh[N_TOK * KV_D];             // K (roped), fp16 hi/lo
__device__ __half g_Kl[N_TOK * KV_D];
__device__ __half g_Vth[KV_D * N_TOK];            // Vt [kv][d][n], fp16 hi/lo
__device__ __half g_Vtl[KV_D * N_TOK];
__device__ __half g_WqTh[D_MODEL * D_MODEL];
__device__ __half g_WqTl[D_MODEL * D_MODEL];
__device__ __half g_WkTh[KV_D * D_MODEL];
__device__ __half g_WkTl[KV_D * D_MODEL];
__device__ __half g_WvTh[KV_D * D_MODEL];
__device__ __half g_WvTl[KV_D * D_MODEL];
__device__ __half g_WoTh[D_MODEL * D_MODEL];
__device__ __half g_WoTl[D_MODEL * D_MODEL];
__device__ float2 g_rope[N_TOK * 64];

__device__ __forceinline__ uint32_t smem_u32(const void* p) {
    uint32_t a;
    asm("{ .reg .u64 t; cvta.to.shared.u64 t, %1; cvt.u32.u64 %0, t; }"
        : "=r"(a) : "l"(p));
    return a;
}

#define LDSM4(r, addr)                                                        \
    asm volatile("ldmatrix.sync.aligned.m8n8.x4.shared.b16 {%0,%1,%2,%3}, [%4];" \
                 : "=r"((r)[0]), "=r"((r)[1]), "=r"((r)[2]), "=r"((r)[3])     \
                 : "r"(addr))

#define MMAF16(d, a, b0, b1)                                                  \
    asm volatile("mma.sync.aligned.m16n8k16.row.col.f32.f16.f16.f32 "         \
                 "{%0,%1,%2,%3}, {%4,%5,%6,%7}, {%8,%9}, {%0,%1,%2,%3};"      \
                 : "+f"((d)[0]), "+f"((d)[1]), "+f"((d)[2]), "+f"((d)[3])     \
                 : "r"((a)[0]), "r"((a)[1]), "r"((a)[2]), "r"((a)[3]),        \
                   "r"(b0), "r"(b1))

__device__ __forceinline__ void cpa16(uint32_t dst, const void* src) {
    asm volatile("cp.async.cg.shared.global [%0], [%1], 16;" :: "r"(dst), "l"(src));
}
#define CPA_COMMIT asm volatile("cp.async.commit_group;" ::: "memory")
#define CPA_WAIT(n) asm volatile("cp.async.wait_group %0;" :: "n"(n) : "memory")

__device__ __forceinline__ float fexp(float x) {
    float t = x * 1.4426950408889634f;
    t = fmaxf(t, -126.0f);
    float n = floorf(t);
    float f = t - n;
    float p = 1.5403530393283621e-4f;
    p = fmaf(p, f, 1.3333558146428443e-3f);
    p = fmaf(p, f, 9.6181291076284772e-3f);
    p = fmaf(p, f, 5.5504108664821580e-2f);
    p = fmaf(p, f, 2.4022650695910071e-1f);
    p = fmaf(p, f, 6.9314718055994531e-1f);
    p = fmaf(p, f, 1.0f);
    return __int_as_float(((int)n + 127) << 23) * p;
}

// fp16 hi/lo split of a float pair
__device__ __forceinline__ void hsplit2(float a, float b, __half2& h, __half2& l) {
    __half ha = __float2half(a), hb = __float2half(b);
    h = __halves2half2(ha, hb);
    l = __halves2half2(__float2half(a - __half2float(ha)),
                       __float2half(b - __half2float(hb)));
}

// ---------------------------------------------------------------------------
// Prep: x -> fp16 single | weights -> transposed fp16 hi/lo | rope table.
// ---------------------------------------------------------------------------
__global__ void __launch_bounds__(256) prep_all(
    const float* __restrict__ x, const float* __restrict__ Wq,
    const float* __restrict__ Wk, const float* __restrict__ Wv,
    const float* __restrict__ Wo,
    __half* __restrict__ xs,
    __half* __restrict__ qth, __half* __restrict__ qtl,
    __half* __restrict__ kth, __half* __restrict__ ktl,
    __half* __restrict__ vth, __half* __restrict__ vtl,
    __half* __restrict__ oth, __half* __restrict__ otl,
    float2* __restrict__ tab) {
    const int bid = blockIdx.x;
    const int tid = threadIdx.x;
    if (bid < 4096) {
        int i = (bid * 256 + tid) * 4;
        float4 v = *(const float4*)(x + i);
        __half2* p = (__half2*)(xs + i);
        p[0] = __halves2half2(__float2half(v.x), __float2half(v.y));
        p[1] = __halves2half2(__float2half(v.z), __float2half(v.w));
    } else if (bid < 14336) {
        __shared__ float t[32][33];
        int wb = bid - 4096;
        const float* in; __half *doh, *dol; int Ndim, nx, sid;
        if (wb < 4096)      { in = Wq; doh = qth; dol = qtl; Ndim = D_MODEL; nx = 64; sid = wb; }
        else if (wb < 5120) { in = Wk; doh = kth; dol = ktl; Ndim = KV_D;   nx = 16; sid = wb - 4096; }
        else if (wb < 6144) { in = Wv; doh = vth; dol = vtl; Ndim = KV_D;   nx = 16; sid = wb - 5120; }
        else                { in = Wo; doh = oth; dol = otl; Ndim = D_MODEL; nx = 64; sid = wb - 6144; }
        int n0 = (sid % nx) * 32, k0 = (sid / nx) * 32;
        int tx = tid & 31, ty = tid >> 5;
#pragma unroll
        for (int i = 0; i < 4; ++i)
            t[ty + 8 * i][tx] = in[(size_t)(k0 + ty + 8 * i) * Ndim + n0 + tx];
        __syncthreads();
#pragma unroll
        for (int i = 0; i < 4; ++i) {
            int nl = ty + 8 * i;
            float v = t[tx][nl];
            __half h = __float2half(v);
            size_t o = (size_t)(n0 + nl) * D_MODEL + k0 + tx;
            doh[o] = h;
            dol[o] = __float2half(v - __half2float(h));
        }
    } else {
        int idx = (bid - 14336) * 256 + tid;
        int t = idx >> 6, i = idx & 63;
        double inv = exp(-9.210340371976184 * ((double)i / 64.0));
        double ang = (double)t * inv;
        double k = floor(ang * 0.15915494309189535);
        float r = (float)(ang - k * 6.283185307179586);
        float s, c;
        sincosf(r, &s, &c);
        tab[idx] = make_float2(c, s);
    }
}

// ---------------------------------------------------------------------------
// cp.async 3-stage fp16 2-pass GEMM core: C = A(single) @ (Bh + Bl)^T.
// BM=BN=128, BK=32. Stage = A | Bh | Bl tiles, 80B row stride.
// ---------------------------------------------------------------------------
#define GRS   80
#define GTB   (128 * GRS)        // 10240 per tile
#define GSBUF (3 * GTB)          // 30720 per stage
#define GSMEM (3 * GSBUF)        // 92160

__device__ __forceinline__ void gemm_issue(
    uint32_t sbase, int slot, int c, int K, int tid,
    const __half* pA, const __half* pBh, const __half* pBl) {
    const __half* bases[3] = {pA, pBh, pBl};
    uint32_t stage = sbase + slot * GSBUF;
#pragma unroll
    for (int t = 0; t < 3; ++t) {
#pragma unroll
        for (int i = 0; i < 2; ++i) {
            int idx = tid + i * 256;
            int r = idx >> 2, cc = idx & 3;
            cpa16(stage + t * GTB + r * GRS + cc * 16,
                  (const char*)bases[t] + ((size_t)r * K + c * 32) * 2 + cc * 16);
        }
    }
}

__device__ __forceinline__ void gemm_core_async(
    const __half* __restrict__ pA,
    const __half* __restrict__ pBh, const __half* __restrict__ pBl,
    int K, uint32_t sbase, float acc[2][8][4]) {
    const int tid = threadIdx.x;
    const int lane = tid & 31;
    const int wid = tid >> 5;
    const int warp_m = wid & 3;
    const int warp_n = wid >> 2;
    const int q = lane >> 3;
    const int rowA = (lane & 7) + (q & 1) * 8;
    const int colA = (q >> 1) * 16;
    const int rowB = (lane & 7) + (q >> 1) * 8;
    const int colB = (q & 1) * 16;

    const int NC = K / 32;
    gemm_issue(sbase, 0, 0, K, tid, pA, pBh, pBl);
    CPA_COMMIT;
    gemm_issue(sbase, 1, 1, K, tid, pA, pBh, pBl);
    CPA_COMMIT;

    int slot = 0;
    for (int c = 0; c < NC; ++c) {
        CPA_WAIT(1);
        __syncthreads();
        if (c + 2 < NC) {
            int ns = slot + 2;
            if (ns >= 3) ns -= 3;
            gemm_issue(sbase, ns, c + 2, K, tid, pA, pBh, pBl);
        }
        CPA_COMMIT;

        const uint32_t sb = sbase + slot * GSBUF;
#pragma unroll
        for (int ks = 0; ks < 2; ++ks) {
            uint32_t a[2][4], bh[4][4], bl[4][4];
#pragma unroll
            for (int im = 0; im < 2; ++im) {
                uint32_t ra = sb + (warp_m * 32 + im * 16 + rowA) * GRS + ks * 32 + colA;
                LDSM4(a[im], ra);
            }
#pragma unroll
            for (int ib = 0; ib < 4; ++ib) {
                uint32_t rb = sb + GTB + (warp_n * 64 + ib * 16 + rowB) * GRS + ks * 32 + colB;
                LDSM4(bh[ib], rb);
                LDSM4(bl[ib], rb + GTB);
            }
#pragma unroll
            for (int im = 0; im < 2; ++im)
#pragma unroll
                for (int j = 0; j < 8; ++j) {
                    const int f = j >> 1, h = (j & 1) * 2;
                    MMAF16(acc[im][j], a[im], bh[f][h], bh[f][h + 1]);
                }
#pragma unroll
            for (int im = 0; im < 2; ++im)
#pragma unroll
                for (int j = 0; j < 8; ++j) {
                    const int f = j >> 1, h = (j & 1) * 2;
                    MMAF16(acc[im][j], a[im], bl[f][h], bl[f][h + 1]);
                }
        }
        if (++slot == 3) slot = 0;
    }
}

// ---- fused Q+K+V projection (384 blocks) ----------------------------------
__global__ void __launch_bounds__(256) hgemm_qkv(
    const __half* __restrict__ A,
    const __half* __restrict__ QBh, const __half* __restrict__ QBl,
    const __half* __restrict__ KBh, const __half* __restrict__ KBl,
    const __half* __restrict__ VBh, const __half* __restrict__ VBl,
    __half* __restrict__ qs,
    __half* __restrict__ kh, __half* __restrict__ kl,
    __half* __restrict__ vth, __half* __restrict__ vtl,
    const float2* __restrict__ tab) {
    extern __shared__ char smem[];
    const uint32_t sbase = smem_u32(smem);
    const int bid = blockIdx.x;
    const int K = D_MODEL;
    int kind, m0, n0;
    const __half *Bh, *Bl;
    if (bid < 256)      { kind = 0; m0 = (bid >> 4) * 128; n0 = (bid & 15) * 128; Bh = QBh; Bl = QBl; }
    else if (bid < 320) { int s = bid - 256; kind = 1; m0 = (s >> 2) * 128; n0 = (s & 3) * 128; Bh = KBh; Bl = KBl; }
    else                { int s = bid - 320; kind = 2; m0 = (s >> 2) * 128; n0 = (s & 3) * 128; Bh = VBh; Bl = VBl; }

    float acc[2][8][4];
#pragma unroll
    for (int im = 0; im < 2; ++im)
#pragma unroll
        for (int j = 0; j < 8; ++j)
#pragma unroll
            for (int e = 0; e < 4; ++e) acc[im][j][e] = 0.f;
    gemm_core_async(A + (size_t)m0 * K, Bh + (size_t)n0 * K, Bl + (size_t)n0 * K,
                    K, sbase, acc);

    const int tid = threadIdx.x;
    const int lane = tid & 31, wid = tid >> 5;
    const int q4 = lane >> 2, l4 = lane & 3;
    if (kind == 0) {
        // Q: rope, store single fp16
#pragma unroll
        for (int im = 0; im < 2; ++im)
#pragma unroll
            for (int j = 0; j < 8; ++j) {
                int row = m0 + (wid & 3) * 32 + im * 16 + q4;
                int col = n0 + (wid >> 2) * 64 + j * 8 + l4 * 2;
#pragma unroll
                for (int rr = 0; rr < 2; ++rr) {
                    int r = row + rr * 8;
                    float v0 = acc[im][j][rr * 2], v1 = acc[im][j][rr * 2 + 1];
                    float2 cs = tab[r * 64 + ((col & 127) >> 1)];
                    float oe = v0 * cs.x - v1 * cs.y;
                    float oo = v0 * cs.y + v1 * cs.x;
                    *(__half2*)(qs + (size_t)r * D_MODEL + col) =
                        __halves2half2(__float2half(oe), __float2half(oo));
                }
            }
    } else if (kind == 1) {
        // K: rope, split fp16 hi/lo
#pragma unroll
        for (int im = 0; im < 2; ++im)
#pragma unroll
            for (int j = 0; j < 8; ++j) {
                int row = m0 + (wid & 3) * 32 + im * 16 + q4;
                int col = n0 + (wid >> 2) * 64 + j * 8 + l4 * 2;
#pragma unroll
                for (int rr = 0; rr < 2; ++rr) {
                    int r = row + rr * 8;
                    float v0 = acc[im][j][rr * 2], v1 = acc[im][j][rr * 2 + 1];
                    float2 cs = tab[r * 64 + ((col & 127) >> 1)];
                    float oe = v0 * cs.x - v1 * cs.y;
                    float oo = v0 * cs.y + v1 * cs.x;
                    __half2 h, l;
                    hsplit2(oe, oo, h, l);
                    *(__half2*)(kh + (size_t)r * KV_D + col) = h;
                    *(__half2*)(kl + (size_t)r * KV_D + col) = l;
                }
            }
    } else {
        // V: transpose via smem, split fp16 hi/lo into [kv][d][n]
        __syncthreads();
        float* tS = (float*)smem;  // [128 d][132]
#pragma unroll
        for (int im = 0; im < 2; ++im)
#pragma unroll
            for (int j = 0; j < 8; ++j) {
                int r = (wid & 3) * 32 + im * 16 + q4;
                int cl = (wid >> 2) * 64 + j * 8 + l4 * 2;
                tS[cl * 132 + r] = acc[im][j][0];
                tS[(cl + 1) * 132 + r] = acc[im][j][1];
                tS[cl * 132 + r + 8] = acc[im][j][2];
                tS[(cl + 1) * 132 + r + 8] = acc[im][j][3];
            }
        __syncthreads();
        const int dkv = n0 >> 7;
        const int d = tid >> 1, half = (tid & 1) * 64;
        size_t dst = (size_t)dkv * 128 * N_TOK + (size_t)d * N_TOK + m0 + half;
#pragma unroll
        for (int k = 0; k < 64; k += 2) {
            __half2 h, l;
            hsplit2(tS[d * 132 + half + k], tS[d * 132 + half + k + 1], h, l);
            *(__half2*)(vth + dst + k) = h;
            *(__half2*)(vtl + dst + k) = l;
        }
    }
}

// ---- output projection ----------------------------------------------------
__global__ void __launch_bounds__(256) hgemm_o(
    const __half* __restrict__ A,
    const __half* __restrict__ Bh, const __half* __restrict__ Bl,
    float* __restrict__ C) {
    extern __shared__ char smem[];
    const uint32_t sbase = smem_u32(smem);
    const int m0 = blockIdx.y * 128, n0 = blockIdx.x * 128;
    const int K = D_MODEL, N = D_MODEL;
    float acc[2][8][4];
#pragma unroll
    for (int im = 0; im < 2; ++im)
#pragma unroll
        for (int j = 0; j < 8; ++j)
#pragma unroll
            for (int e = 0; e < 4; ++e) acc[im][j][e] = 0.f;
    gemm_core_async(A + (size_t)m0 * K, Bh + (size_t)n0 * K, Bl + (size_t)n0 * K,
                    K, sbase, acc);
    const int lane = threadIdx.x & 31, wid = threadIdx.x >> 5;
#pragma unroll
    for (int im = 0; im < 2; ++im)
#pragma unroll
        for (int j = 0; j < 8; ++j) {
            int row = m0 + (wid & 3) * 32 + im * 16 + (lane >> 2);
            int col = n0 + (wid >> 2) * 64 + j * 8 + (lane & 3) * 2;
            *(float2*)(C + (size_t)row * N + col) = make_float2(acc[im][j][0], acc[im][j][1]);
            *(float2*)(C + (size_t)(row + 8) * N + col) = make_float2(acc[im][j][2], acc[im][j][3]);
        }
}

// ---------------------------------------------------------------------------
// Flash attention, fp16 2-pass: Q single (resident), K hi/lo double-buffered,
// V hi/lo pipelined, P single fp16.
// ---------------------------------------------------------------------------
#define RSQ 272
#define RSV 144
#define OQ   0                   // Q single: 128*272 = 34816
#define OKST 34816               // K stages: 2 * 34816 (Kh +0, Kl +17408)
#define OVH  104448              // Vt hi: 128*144 = 18432
#define OVL  122880
#define OP   141312              // P single: 128*144
#define FSMEM 159744

__global__ void __launch_bounds__(256, 1) flash_mma(
    const __half* __restrict__ Qs,
    const __half* __restrict__ Kh, const __half* __restrict__ Kl,
    const __half* __restrict__ Vth, const __half* __restrict__ Vtl,
    __half* __restrict__ cs) {
    const int qt = gridDim.x - 1 - blockIdx.x;
    const int h  = blockIdx.y;
    const int g  = h >> 2, kv = h & 3;
    const int qcol0 = g * 512 + kv * 128;
    const int kcol0 = kv * 128;
    const int ocol0 = (kv * 4 + g) * 128;
    const __half* vh = Vth + (size_t)kv * 128 * N_TOK;
    const __half* vl = Vtl + (size_t)kv * 128 * N_TOK;

    extern __shared__ char smem[];
    const uint32_t sbase = smem_u32(smem);

    const int tid = threadIdx.x;
    const int lane = tid & 31;
    const int warp_m = tid >> 5;
    const int q4 = lane >> 2, l4 = lane & 3;
    const int qq = lane >> 3;
    const int rowA = (lane & 7) + (qq & 1) * 8;
    const int colA = (qq >> 1) * 16;
    const int rowB = (lane & 7) + (qq >> 1) * 8;
    const int colB = (qq & 1) * 16;
    const float SCALE = 0.08838834764831845f;

    // Q tile (single fp16) -> smem
#pragma unroll
    for (int i = 0; i < 8; ++i) {
        int idx = tid + i * 256;
        int r = idx >> 4, c = idx & 15;
        size_t go = (size_t)(qt * 128 + r) * D_MODEL + qcol0 + c * 8;
        *(uint4*)(smem + OQ + r * RSQ + c * 16) = *(const uint4*)(Qs + go);
    }

    // issue K(0)
    {
#pragma unroll
        for (int i = 0; i < 8; ++i) {
            int idx = tid + i * 256;
            int half = i >> 2;
            int li = idx & 1023;
            int r = li >> 4, c = li & 15;
            const __half* src = half ? Kl : Kh;
            cpa16(sbase + OKST + half * 17408 + r * RSQ + c * 16,
                  src + (size_t)r * KV_D + kcol0 + c * 8);
        }
        CPA_COMMIT;
    }

    float o[16][4];
#pragma unroll
    for (int f = 0; f < 16; ++f)
#pragma unroll
        for (int e = 0; e < 4; ++e) o[f][e] = 0.f;
    float m0 = -1e30f, m1 = -1e30f, l0 = 0.f, l1 = 0.f;

    const int nkt = 2 * qt + 2;
    for (int kt = 0; kt < nkt; ++kt) {
        __syncthreads();

        // issue V(kt) and K(kt+1)
#pragma unroll
        for (int i = 0; i < 8; ++i) {
            int idx = tid + i * 256;
            int half = i >> 2;
            int li = idx & 1023;
            int r = li >> 3, c = li & 7;
            const __half* src = half ? vl : vh;
            cpa16(sbase + (half ? OVL : OVH) + r * RSV + c * 16,
                  src + (size_t)r * N_TOK + kt * 64 + c * 8);
        }
        if (kt + 1 < nkt) {
            uint32_t kst = sbase + OKST + ((kt + 1) & 1) * 34816;
#pragma unroll
            for (int i = 0; i < 8; ++i) {
                int idx = tid + i * 256;
                int half = i >> 2;
                int li = idx & 1023;
                int r = li >> 4, c = li & 15;
                const __half* src = half ? Kl : Kh;
                cpa16(kst + half * 17408 + r * RSQ + c * 16,
                      src + (size_t)((kt + 1) * 64 + r) * KV_D + kcol0 + c * 8);
            }
        }
        CPA_COMMIT;

        CPA_WAIT(1);
        __syncthreads();

        const int rbase = qt * 128 + warp_m * 16;
        const bool active = (kt * 64) <= (rbase + 15);
        const uint32_t kst = sbase + OKST + (kt & 1) * 34816;

        if (active) {
            float sacc[8][4];
#pragma unroll
            for (int j = 0; j < 8; ++j)
#pragma unroll
                for (int e = 0; e < 4; ++e) sacc[j][e] = 0.f;
#pragma unroll
            for (int ks = 0; ks < 8; ++ks) {
                uint32_t a[4];
                uint32_t ra = sbase + OQ + (warp_m * 16 + rowA) * RSQ + ks * 32 + colA;
                LDSM4(a, ra);
#pragma unroll
                for (int p = 0; p < 2; ++p) {
                    uint32_t bh[2][4], bl[2][4];
#pragma unroll
                    for (int u = 0; u < 2; ++u) {
                        uint32_t rb = kst + ((p * 2 + u) * 16 + rowB) * RSQ + ks * 32 + colB;
                        LDSM4(bh[u], rb);
                        LDSM4(bl[u], rb + 17408);
                    }
#pragma unroll
                    for (int u = 0; u < 2; ++u)
#pragma unroll
                        for (int half = 0; half < 2; ++half)
                            MMAF16(sacc[(p * 2 + u) * 2 + half], a, bh[u][half * 2], bh[u][half * 2 + 1]);
#pragma unroll
                    for (int u = 0; u < 2; ++u)
#pragma unroll
                        for (int half = 0; half < 2; ++half)
                            MMAF16(sacc[(p * 2 + u) * 2 + half], a, bl[u][half * 2], bl[u][half * 2 + 1]);
                }
            }
            const bool needMask = (kt * 64 + 63) > rbase;
#pragma unroll
            for (int j = 0; j < 8; ++j)
#pragma unroll
                for (int e = 0; e < 4; ++e) {
                    float v = sacc[j][e] * SCALE;
                    if (needMask) {
                        int rg = rbase + q4 + (e >> 1) * 8;
                        int kg = kt * 64 + j * 8 + l4 * 2 + (e & 1);
                        if (kg > rg) v = -1e30f;
                    }
                    sacc[j][e] = v;
                }
            float mx0 = -1e30f, mx1 = -1e30f;
#pragma unroll
            for (int j = 0; j < 8; ++j) {
                mx0 = fmaxf(mx0, fmaxf(sacc[j][0], sacc[j][1]));
                mx1 = fmaxf(mx1, fmaxf(sacc[j][2], sacc[j][3]));
            }
            mx0 = fmaxf(mx0, __shfl_xor_sync(0xffffffffu, mx0, 1));
            mx0 = fmaxf(mx0, __shfl_xor_sync(0xffffffffu, mx0, 2));
            mx1 = fmaxf(mx1, __shfl_xor_sync(0xffffffffu, mx1, 1));
            mx1 = fmaxf(mx1, __shfl_xor_sync(0xffffffffu, mx1, 2));
            float nm0 = fmaxf(m0, mx0), nm1 = fmaxf(m1, mx1);
            float corr0 = fexp(m0 - nm0), corr1 = fexp(m1 - nm1);
            m0 = nm0; m1 = nm1;
            float s0 = 0.f, s1 = 0.f;
            uint32_t prow0 = sbase + OP + (warp_m * 16 + q4) * RSV + l4 * 4;
            uint32_t prow1 = prow0 + 8 * RSV;
#pragma unroll
            for (int j = 0; j < 8; ++j) {
                float p00 = fexp(sacc[j][0] - m0);
                float p01 = fexp(sacc[j][1] - m0);
                float p10 = fexp(sacc[j][2] - m1);
                float p11 = fexp(sacc[j][3] - m1);
                s0 += p00 + p01; s1 += p10 + p11;
                __half2 hp0 = __halves2half2(__float2half(p00), __float2half(p01));
                __half2 hp1 = __halves2half2(__float2half(p10), __float2half(p11));
                asm volatile("st.shared.b32 [%0], %1;" :: "r"(prow0 + j * 16), "r"(*(uint32_t*)&hp0));
                asm volatile("st.shared.b32 [%0], %1;" :: "r"(prow1 + j * 16), "r"(*(uint32_t*)&hp1));
            }
            s0 += __shfl_xor_sync(0xffffffffu, s0, 1);
            s0 += __shfl_xor_sync(0xffffffffu, s0, 2);
            s1 += __shfl_xor_sync(0xffffffffu, s1, 1);
            s1 += __shfl_xor_sync(0xffffffffu, s1, 2);
            l0 = l0 * corr0 + s0;
            l1 = l1 * corr1 + s1;
#pragma unroll
            for (int f = 0; f < 16; ++f) {
                o[f][0] *= corr0; o[f][1] *= corr0;
                o[f][2] *= corr1; o[f][3] *= corr1;
            }
        }

        CPA_WAIT(0);
        __syncthreads();

        if (active) {
#pragma unroll
            for (int ks = 0; ks < 4; ++ks) {
                uint32_t pa[4];
                uint32_t raddr = sbase + OP + (warp_m * 16 + rowA) * RSV + ks * 32 + colA;
                LDSM4(pa, raddr);
#pragma unroll
                for (int p = 0; p < 4; ++p) {
                    uint32_t vb[2][4], vbl[2][4];
#pragma unroll
                    for (int u = 0; u < 2; ++u) {
                        uint32_t b0 = sbase + OVH + ((p * 2 + u) * 16 + rowB) * RSV + ks * 32 + colB;
                        LDSM4(vb[u], b0);
                        LDSM4(vbl[u], b0 + (OVL - OVH));
                    }
#pragma unroll
                    for (int u = 0; u < 2; ++u)
#pragma unroll
                        for (int half = 0; half < 2; ++half)
                            MMAF16(o[(p * 2 + u) * 2 + half], pa, vb[u][half * 2], vb[u][half * 2 + 1]);
#pragma unroll
                    for (int u = 0; u < 2; ++u)
#pragma unroll
                        for (int half = 0; half < 2; ++half)
                            MMAF16(o[(p * 2 + u) * 2 + half], pa, vbl[u][half * 2], vbl[u][half * 2 + 1]);
                }
            }
        }
    }

    float i0 = 1.f / l0, i1 = 1.f / l1;
    int row0 = qt * 128 + warp_m * 16 + q4;
#pragma unroll
    for (int f = 0; f < 16; ++f) {
        int col = ocol0 + f * 8 + l4 * 2;
        *(__half2*)(cs + (size_t)row0 * D_MODEL + col) =
            __halves2half2(__float2half(o[f][0] * i0), __float2half(o[f][1] * i0));
        *(__half2*)(cs + (size_t)(row0 + 8) * D_MODEL + col) =
            __halves2half2(__float2half(o[f][2] * i1), __float2half(o[f][3] * i1));
    }
}

// ---------------------------------------------------------------------------
extern "C" void kernel_launch(void* const* d_in, const int* in_sizes, int n_in,
                              void* d_out, int out_size) {
    const float* x  = (const float*)d_in[0];
    const float* Wq = (const float*)d_in[1];
    const float* Wk = (const float*)d_in[2];
    const float* Wv = (const float*)d_in[3];
    const float* Wo = (const float*)d_in[4];
    float* out = (float*)d_out;

    __half *xs, *cs, *qs, *kh, *kl, *vth, *vtl;
    __half *qth, *qtl, *kth, *ktl, *vwh, *vwl, *oth, *otl;
    float2* tab;
    cudaGetSymbolAddress((void**)&xs, g_xs);
    cudaGetSymbolAddress((void**)&cs, g_cs);
    cudaGetSymbolAddress((void**)&qs, g_Qs);
    cudaGetSymbolAddress((void**)&kh, g_Kh);   cudaGetSymbolAddress((void**)&kl, g_Kl);
    cudaGetSymbolAddress((void**)&vth, g_Vth); cudaGetSymbolAddress((void**)&vtl, g_Vtl);
    cudaGetSymbolAddress((void**)&qth, g_WqTh); cudaGetSymbolAddress((void**)&qtl, g_WqTl);
    cudaGetSymbolAddress((void**)&kth, g_WkTh); cudaGetSymbolAddress((void**)&ktl, g_WkTl);
    cudaGetSymbolAddress((void**)&vwh, g_WvTh); cudaGetSymbolAddress((void**)&vwl, g_WvTl);
    cudaGetSymbolAddress((void**)&oth, g_WoTh); cudaGetSymbolAddress((void**)&otl, g_WoTl);
    cudaGetSymbolAddress((void**)&tab, g_rope);

    cudaFuncSetAttribute(hgemm_qkv, cudaFuncAttributeMaxDynamicSharedMemorySize, GSMEM);
    cudaFuncSetAttribute(hgemm_o,   cudaFuncAttributeMaxDynamicSharedMemorySize, GSMEM);
    cudaFuncSetAttribute(flash_mma, cudaFuncAttributeMaxDynamicSharedMemorySize, FSMEM);

    prep_all<<<14848, 256>>>(x, Wq, Wk, Wv, Wo, xs, qth, qtl, kth, ktl,
                             vwh, vwl, oth, otl, tab);
    hgemm_qkv<<<384, 256, GSMEM>>>(xs, qth, qtl, kth, ktl, vwh, vwl,
                                   qs, kh, kl, vth, vtl, tab);
    flash_mma<<<dim3(N_TOK / 128, 16), 256, FSMEM>>>(qs, kh, kl, vth, vtl, cs);
    hgemm_o<<<dim3(16, 16), 256, GSMEM>>>(cs, oth, otl, out);

    (void)in_sizes; (void)n_in; (void)out_size;
}

// round 10
// speedup vs baseline: 1.7225x; 1.2201x over previous
#include <cuda_runtime.h>
#include <cuda_fp16.h>
#include <math.h>
#include <stdint.h>

#define N_TOK   2048
#define D_MODEL 2048
#define KV_D    512

// ---------------- scratch ---------------------------------------------------
__device__ __half g_xs[N_TOK * D_MODEL];
__device__ __half g_cs[N_TOK * D_MODEL];
__device__ __half g_Qs[N_TOK * D_MODEL];
__device__ __half g_Kh[N_TOK * KV_D];
__device__ __half g_Kl[N_TOK * KV_D];
__device__ __half g_Vth[KV_D * N_TOK];
__device__ __half g_Vtl[KV_D * N_TOK];
__device__ __half g_WqTh[D_MODEL * D_MODEL];
__device__ __half g_WkTh[KV_D * D_MODEL];
__device__ __half g_WkTl[KV_D * D_MODEL];
__device__ __half g_WvTh[KV_D * D_MODEL];
__device__ __half g_WvTl[KV_D * D_MODEL];
__device__ __half g_WoTh[D_MODEL * D_MODEL];
__device__ float2 g_rope[N_TOK * 64];

__device__ __forceinline__ uint32_t smem_u32(const void* p) {
    uint32_t a;
    asm("{ .reg .u64 t; cvta.to.shared.u64 t, %1; cvt.u32.u64 %0, t; }"
        : "=r"(a) : "l"(p));
    return a;
}

#define LDSM4(r, addr)                                                        \
    asm volatile("ldmatrix.sync.aligned.m8n8.x4.shared.b16 {%0,%1,%2,%3}, [%4];" \
                 : "=r"((r)[0]), "=r"((r)[1]), "=r"((r)[2]), "=r"((r)[3])     \
                 : "r"(addr))

#define MMAF16(d, a, b0, b1)                                                  \
    asm volatile("mma.sync.aligned.m16n8k16.row.col.f32.f16.f16.f32 "         \
                 "{%0,%1,%2,%3}, {%4,%5,%6,%7}, {%8,%9}, {%0,%1,%2,%3};"      \
                 : "+f"((d)[0]), "+f"((d)[1]), "+f"((d)[2]), "+f"((d)[3])     \
                 : "r"((a)[0]), "r"((a)[1]), "r"((a)[2]), "r"((a)[3]),        \
                   "r"(b0), "r"(b1))

__device__ __forceinline__ void cpa16(uint32_t dst, const void* src) {
    asm volatile("cp.async.cg.shared.global [%0], [%1], 16;" :: "r"(dst), "l"(src));
}
#define CPA_COMMIT asm volatile("cp.async.commit_group;" ::: "memory")
#define CPA_WAIT(n) asm volatile("cp.async.wait_group %0;" :: "n"(n) : "memory")

__device__ __forceinline__ float fexp(float x) {
    float t = x * 1.4426950408889634f;
    t = fmaxf(t, -126.0f);
    float n = floorf(t);
    float f = t - n;
    float p = 1.5403530393283621e-4f;
    p = fmaf(p, f, 1.3333558146428443e-3f);
    p = fmaf(p, f, 9.6181291076284772e-3f);
    p = fmaf(p, f, 5.5504108664821580e-2f);
    p = fmaf(p, f, 2.4022650695910071e-1f);
    p = fmaf(p, f, 6.9314718055994531e-1f);
    p = fmaf(p, f, 1.0f);
    return __int_as_float(((int)n + 127) << 23) * p;
}

__device__ __forceinline__ void hsplit2(float a, float b, __half2& h, __half2& l) {
    __half ha = __float2half(a), hb = __float2half(b);
    h = __halves2half2(ha, hb);
    l = __halves2half2(__float2half(a - __half2float(ha)),
                       __float2half(b - __half2float(hb)));
}

// ---------------------------------------------------------------------------
// Prep: x -> fp16 | Wq/Wo -> transposed fp16 single; Wk/Wv -> hi/lo | rope tab
// ---------------------------------------------------------------------------
__global__ void __launch_bounds__(256) prep_all(
    const float* __restrict__ x, const float* __restrict__ Wq,
    const float* __restrict__ Wk, const float* __restrict__ Wv,
    const float* __restrict__ Wo,
    __half* __restrict__ xs,
    __half* __restrict__ qth,
    __half* __restrict__ kth, __half* __restrict__ ktl,
    __half* __restrict__ vth, __half* __restrict__ vtl,
    __half* __restrict__ oth,
    float2* __restrict__ tab) {
    const int bid = blockIdx.x;
    const int tid = threadIdx.x;
    if (bid < 4096) {
        int i = (bid * 256 + tid) * 4;
        float4 v = *(const float4*)(x + i);
        __half2* p = (__half2*)(xs + i);
        p[0] = __halves2half2(__float2half(v.x), __float2half(v.y));
        p[1] = __halves2half2(__float2half(v.z), __float2half(v.w));
    } else if (bid < 14336) {
        __shared__ float t[32][33];
        int wb = bid - 4096;
        const float* in; __half *doh, *dol; int Ndim, nx, sid;
        if (wb < 4096)      { in = Wq; doh = qth; dol = 0;   Ndim = D_MODEL; nx = 64; sid = wb; }
        else if (wb < 5120) { in = Wk; doh = kth; dol = ktl; Ndim = KV_D;   nx = 16; sid = wb - 4096; }
        else if (wb < 6144) { in = Wv; doh = vth; dol = vtl; Ndim = KV_D;   nx = 16; sid = wb - 5120; }
        else                { in = Wo; doh = oth; dol = 0;   Ndim = D_MODEL; nx = 64; sid = wb - 6144; }
        int n0 = (sid % nx) * 32, k0 = (sid / nx) * 32;
        int tx = tid & 31, ty = tid >> 5;
#pragma unroll
        for (int i = 0; i < 4; ++i)
            t[ty + 8 * i][tx] = in[(size_t)(k0 + ty + 8 * i) * Ndim + n0 + tx];
        __syncthreads();
#pragma unroll
        for (int i = 0; i < 4; ++i) {
            int nl = ty + 8 * i;
            float v = t[tx][nl];
            __half h = __float2half(v);
            size_t o = (size_t)(n0 + nl) * D_MODEL + k0 + tx;
            doh[o] = h;
            if (dol) dol[o] = __float2half(v - __half2float(h));
        }
    } else {
        int idx = (bid - 14336) * 256 + tid;
        int t = idx >> 6, i = idx & 63;
        double inv = exp(-9.210340371976184 * ((double)i / 64.0));
        double ang = (double)t * inv;
        double k = floor(ang * 0.15915494309189535);
        float r = (float)(ang - k * 6.283185307179586);
        float s, c;
        sincosf(r, &s, &c);
        tab[idx] = make_float2(c, s);
    }
}

// ---------------------------------------------------------------------------
// cp.async 3-stage GEMM cores. BM=BN=128, BK=32, 256 threads.
// 1-pass: C = A @ B^T (both single fp16). 2-pass: C = A @ (Bh+Bl)^T.
// ---------------------------------------------------------------------------
#define GRS    80
#define GTB    (128 * GRS)
#define GSB1   (2 * GTB)         // 1-pass stage: A|B
#define GSB2   (3 * GTB)         // 2-pass stage: A|Bh|Bl
#define GSMEM1 (3 * GSB1)        // 61440
#define GSMEM2 (3 * GSB2)        // 92160

template <int NT>
__device__ __forceinline__ void gemm_issue(
    uint32_t sbase, int stride, int slot, int c, int K, int tid,
    const __half* const* bases) {
    uint32_t stage = sbase + slot * stride;
#pragma unroll
    for (int t = 0; t < NT; ++t) {
#pragma unroll
        for (int i = 0; i < 2; ++i) {
            int idx = tid + i * 256;
            int r = idx >> 2, cc = idx & 3;
            cpa16(stage + t * GTB + r * GRS + cc * 16,
                  (const char*)bases[t] + ((size_t)r * K + c * 32) * 2 + cc * 16);
        }
    }
}

template <bool TWOPASS>
__device__ __forceinline__ void gemm_core(
    const __half* __restrict__ pA,
    const __half* __restrict__ pBh, const __half* __restrict__ pBl,
    int K, uint32_t sbase, float acc[2][8][4]) {
    constexpr int NT = TWOPASS ? 3 : 2;
    constexpr int STRIDE = NT * GTB;
    const __half* bases[NT];
    bases[0] = pA; bases[1] = pBh;
    if (TWOPASS) bases[2] = pBl;

    const int tid = threadIdx.x;
    const int lane = tid & 31;
    const int wid = tid >> 5;
    const int warp_m = wid & 3;
    const int warp_n = wid >> 2;
    const int q = lane >> 3;
    const int rowA = (lane & 7) + (q & 1) * 8;
    const int colA = (q >> 1) * 16;
    const int rowB = (lane & 7) + (q >> 1) * 8;
    const int colB = (q & 1) * 16;

    const int NC = K / 32;
    gemm_issue<NT>(sbase, STRIDE, 0, 0, K, tid, bases);
    CPA_COMMIT;
    gemm_issue<NT>(sbase, STRIDE, 1, 1, K, tid, bases);
    CPA_COMMIT;

    int slot = 0;
    for (int c = 0; c < NC; ++c) {
        CPA_WAIT(1);
        __syncthreads();
        if (c + 2 < NC) {
            int ns = slot + 2;
            if (ns >= 3) ns -= 3;
            gemm_issue<NT>(sbase, STRIDE, ns, c + 2, K, tid, bases);
        }
        CPA_COMMIT;

        const uint32_t sb = sbase + slot * STRIDE;
#pragma unroll
        for (int ks = 0; ks < 2; ++ks) {
            uint32_t a[2][4], bh[4][4], bl[4][4];
#pragma unroll
            for (int im = 0; im < 2; ++im) {
                uint32_t ra = sb + (warp_m * 32 + im * 16 + rowA) * GRS + ks * 32 + colA;
                LDSM4(a[im], ra);
            }
#pragma unroll
            for (int ib = 0; ib < 4; ++ib) {
                uint32_t rb = sb + GTB + (warp_n * 64 + ib * 16 + rowB) * GRS + ks * 32 + colB;
                LDSM4(bh[ib], rb);
                if (TWOPASS) LDSM4(bl[ib], rb + GTB);
            }
#pragma unroll
            for (int im = 0; im < 2; ++im)
#pragma unroll
                for (int j = 0; j < 8; ++j) {
                    const int f = j >> 1, h = (j & 1) * 2;
                    MMAF16(acc[im][j], a[im], bh[f][h], bh[f][h + 1]);
                }
            if (TWOPASS) {
#pragma unroll
                for (int im = 0; im < 2; ++im)
#pragma unroll
                    for (int j = 0; j < 8; ++j) {
                        const int f = j >> 1, h = (j & 1) * 2;
                        MMAF16(acc[im][j], a[im], bl[f][h], bl[f][h + 1]);
                    }
            }
        }
        if (++slot == 3) slot = 0;
    }
}

// ---- fused Q+K+V projection (384 blocks) ----------------------------------
__global__ void __launch_bounds__(256) hgemm_qkv(
    const __half* __restrict__ A,
    const __half* __restrict__ QBh,
    const __half* __restrict__ KBh, const __half* __restrict__ KBl,
    const __half* __restrict__ VBh, const __half* __restrict__ VBl,
    __half* __restrict__ qs,
    __half* __restrict__ kh, __half* __restrict__ kl,
    __half* __restrict__ vth, __half* __restrict__ vtl,
    const float2* __restrict__ tab) {
    extern __shared__ char smem[];
    const uint32_t sbase = smem_u32(smem);
    const int bid = blockIdx.x;
    const int K = D_MODEL;
    int kind, m0, n0;
    if (bid < 256)      { kind = 0; m0 = (bid >> 4) * 128; n0 = (bid & 15) * 128; }
    else if (bid < 320) { int s = bid - 256; kind = 1; m0 = (s >> 2) * 128; n0 = (s & 3) * 128; }
    else                { int s = bid - 320; kind = 2; m0 = (s >> 2) * 128; n0 = (s & 3) * 128; }

    float acc[2][8][4];
#pragma unroll
    for (int im = 0; im < 2; ++im)
#pragma unroll
        for (int j = 0; j < 8; ++j)
#pragma unroll
            for (int e = 0; e < 4; ++e) acc[im][j][e] = 0.f;

    if (kind == 0) {
        gemm_core<false>(A + (size_t)m0 * K, QBh + (size_t)n0 * K, 0, K, sbase, acc);
    } else if (kind == 1) {
        gemm_core<true>(A + (size_t)m0 * K, KBh + (size_t)n0 * K,
                        KBl + (size_t)n0 * K, K, sbase, acc);
    } else {
        gemm_core<true>(A + (size_t)m0 * K, VBh + (size_t)n0 * K,
                        VBl + (size_t)n0 * K, K, sbase, acc);
    }

    const int tid = threadIdx.x;
    const int lane = tid & 31, wid = tid >> 5;
    const int q4 = lane >> 2, l4 = lane & 3;
    if (kind == 0) {
#pragma unroll
        for (int im = 0; im < 2; ++im)
#pragma unroll
            for (int j = 0; j < 8; ++j) {
                int row = m0 + (wid & 3) * 32 + im * 16 + q4;
                int col = n0 + (wid >> 2) * 64 + j * 8 + l4 * 2;
#pragma unroll
                for (int rr = 0; rr < 2; ++rr) {
                    int r = row + rr * 8;
                    float v0 = acc[im][j][rr * 2], v1 = acc[im][j][rr * 2 + 1];
                    float2 cs = tab[r * 64 + ((col & 127) >> 1)];
                    float oe = v0 * cs.x - v1 * cs.y;
                    float oo = v0 * cs.y + v1 * cs.x;
                    *(__half2*)(qs + (size_t)r * D_MODEL + col) =
                        __halves2half2(__float2half(oe), __float2half(oo));
                }
            }
    } else if (kind == 1) {
#pragma unroll
        for (int im = 0; im < 2; ++im)
#pragma unroll
            for (int j = 0; j < 8; ++j) {
                int row = m0 + (wid & 3) * 32 + im * 16 + q4;
                int col = n0 + (wid >> 2) * 64 + j * 8 + l4 * 2;
#pragma unroll
                for (int rr = 0; rr < 2; ++rr) {
                    int r = row + rr * 8;
                    float v0 = acc[im][j][rr * 2], v1 = acc[im][j][rr * 2 + 1];
                    float2 cs = tab[r * 64 + ((col & 127) >> 1)];
                    float oe = v0 * cs.x - v1 * cs.y;
                    float oo = v0 * cs.y + v1 * cs.x;
                    __half2 h, l;
                    hsplit2(oe, oo, h, l);
                    *(__half2*)(kh + (size_t)r * KV_D + col) = h;
                    *(__half2*)(kl + (size_t)r * KV_D + col) = l;
                }
            }
    } else {
        __syncthreads();
        float* tS = (float*)smem;  // [128][132]
#pragma unroll
        for (int im = 0; im < 2; ++im)
#pragma unroll
            for (int j = 0; j < 8; ++j) {
                int r = (wid & 3) * 32 + im * 16 + q4;
                int cl = (wid >> 2) * 64 + j * 8 + l4 * 2;
                tS[cl * 132 + r] = acc[im][j][0];
                tS[(cl + 1) * 132 + r] = acc[im][j][1];
                tS[cl * 132 + r + 8] = acc[im][j][2];
                tS[(cl + 1) * 132 + r + 8] = acc[im][j][3];
            }
        __syncthreads();
        const int dkv = n0 >> 7;
        const int d = tid >> 1, half = (tid & 1) * 64;
        size_t dst = (size_t)dkv * 128 * N_TOK + (size_t)d * N_TOK + m0 + half;
#pragma unroll
        for (int k = 0; k < 64; k += 2) {
            __half2 h, l;
            hsplit2(tS[d * 132 + half + k], tS[d * 132 + half + k + 1], h, l);
            *(__half2*)(vth + dst + k) = h;
            *(__half2*)(vtl + dst + k) = l;
        }
    }
}

// ---- output projection: single-pass ---------------------------------------
__global__ void __launch_bounds__(256) hgemm_o(
    const __half* __restrict__ A, const __half* __restrict__ Bh,
    float* __restrict__ C) {
    extern __shared__ char smem[];
    const uint32_t sbase = smem_u32(smem);
    const int m0 = blockIdx.y * 128, n0 = blockIdx.x * 128;
    const int K = D_MODEL, N = D_MODEL;
    float acc[2][8][4];
#pragma unroll
    for (int im = 0; im < 2; ++im)
#pragma unroll
        for (int j = 0; j < 8; ++j)
#pragma unroll
            for (int e = 0; e < 4; ++e) acc[im][j][e] = 0.f;
    gemm_core<false>(A + (size_t)m0 * K, Bh + (size_t)n0 * K, 0, K, sbase, acc);
    const int lane = threadIdx.x & 31, wid = threadIdx.x >> 5;
#pragma unroll
    for (int im = 0; im < 2; ++im)
#pragma unroll
        for (int j = 0; j < 8; ++j) {
            int row = m0 + (wid & 3) * 32 + im * 16 + (lane >> 2);
            int col = n0 + (wid >> 2) * 64 + j * 8 + (lane & 3) * 2;
            *(float2*)(C + (size_t)row * N + col) = make_float2(acc[im][j][0], acc[im][j][1]);
            *(float2*)(C + (size_t)(row + 8) * N + col) = make_float2(acc[im][j][2], acc[im][j][3]);
        }
}

// ---------------------------------------------------------------------------
// Flash attention (unchanged from R9).
// ---------------------------------------------------------------------------
#define RSQ 272
#define RSV 144
#define OQ   0
#define OKST 34816
#define OVH  104448
#define OVL  122880
#define OP   141312
#define FSMEM 159744

__global__ void __launch_bounds__(256, 1) flash_mma(
    const __half* __restrict__ Qs,
    const __half* __restrict__ Kh, const __half* __restrict__ Kl,
    const __half* __restrict__ Vth, const __half* __restrict__ Vtl,
    __half* __restrict__ cs) {
    const int qt = gridDim.x - 1 - blockIdx.x;
    const int h  = blockIdx.y;
    const int g  = h >> 2, kv = h & 3;
    const int qcol0 = g * 512 + kv * 128;
    const int kcol0 = kv * 128;
    const int ocol0 = (kv * 4 + g) * 128;
    const __half* vh = Vth + (size_t)kv * 128 * N_TOK;
    const __half* vl = Vtl + (size_t)kv * 128 * N_TOK;

    extern __shared__ char smem[];
    const uint32_t sbase = smem_u32(smem);

    const int tid = threadIdx.x;
    const int lane = tid & 31;
    const int warp_m = tid >> 5;
    const int q4 = lane >> 2, l4 = lane & 3;
    const int qq = lane >> 3;
    const int rowA = (lane & 7) + (qq & 1) * 8;
    const int colA = (qq >> 1) * 16;
    const int rowB = (lane & 7) + (qq >> 1) * 8;
    const int colB = (qq & 1) * 16;
    const float SCALE = 0.08838834764831845f;

#pragma unroll
    for (int i = 0; i < 8; ++i) {
        int idx = tid + i * 256;
        int r = idx >> 4, c = idx & 15;
        size_t go = (size_t)(qt * 128 + r) * D_MODEL + qcol0 + c * 8;
        *(uint4*)(smem + OQ + r * RSQ + c * 16) = *(const uint4*)(Qs + go);
    }

    {
#pragma unroll
        for (int i = 0; i < 8; ++i) {
            int idx = tid + i * 256;
            int half = i >> 2;
            int li = idx & 1023;
            int r = li >> 4, c = li & 15;
            const __half* src = half ? Kl : Kh;
            cpa16(sbase + OKST + half * 17408 + r * RSQ + c * 16,
                  src + (size_t)r * KV_D + kcol0 + c * 8);
        }
        CPA_COMMIT;
    }

    float o[16][4];
#pragma unroll
    for (int f = 0; f < 16; ++f)
#pragma unroll
        for (int e = 0; e < 4; ++e) o[f][e] = 0.f;
    float m0 = -1e30f, m1 = -1e30f, l0 = 0.f, l1 = 0.f;

    const int nkt = 2 * qt + 2;
    for (int kt = 0; kt < nkt; ++kt) {
        __syncthreads();

#pragma unroll
        for (int i = 0; i < 8; ++i) {
            int idx = tid + i * 256;
            int half = i >> 2;
            int li = idx & 1023;
            int r = li >> 3, c = li & 7;
            const __half* src = half ? vl : vh;
            cpa16(sbase + (half ? OVL : OVH) + r * RSV + c * 16,
                  src + (size_t)r * N_TOK + kt * 64 + c * 8);
        }
        if (kt + 1 < nkt) {
            uint32_t kst = sbase + OKST + ((kt + 1) & 1) * 34816;
#pragma unroll
            for (int i = 0; i < 8; ++i) {
                int idx = tid + i * 256;
                int half = i >> 2;
                int li = idx & 1023;
                int r = li >> 4, c = li & 15;
                const __half* src = half ? Kl : Kh;
                cpa16(kst + half * 17408 + r * RSQ + c * 16,
                      src + (size_t)((kt + 1) * 64 + r) * KV_D + kcol0 + c * 8);
            }
        }
        CPA_COMMIT;

        CPA_WAIT(1);
        __syncthreads();

        const int rbase = qt * 128 + warp_m * 16;
        const bool active = (kt * 64) <= (rbase + 15);
        const uint32_t kst = sbase + OKST + (kt & 1) * 34816;

        if (active) {
            float sacc[8][4];
#pragma unroll
            for (int j = 0; j < 8; ++j)
#pragma unroll
                for (int e = 0; e < 4; ++e) sacc[j][e] = 0.f;
#pragma unroll
            for (int ks = 0; ks < 8; ++ks) {
                uint32_t a[4];
                uint32_t ra = sbase + OQ + (warp_m * 16 + rowA) * RSQ + ks * 32 + colA;
                LDSM4(a, ra);
#pragma unroll
                for (int p = 0; p < 2; ++p) {
                    uint32_t bh[2][4], bl[2][4];
#pragma unroll
                    for (int u = 0; u < 2; ++u) {
                        uint32_t rb = kst + ((p * 2 + u) * 16 + rowB) * RSQ + ks * 32 + colB;
                        LDSM4(bh[u], rb);
                        LDSM4(bl[u], rb + 17408);
                    }
#pragma unroll
                    for (int u = 0; u < 2; ++u)
#pragma unroll
                        for (int half = 0; half < 2; ++half)
                            MMAF16(sacc[(p * 2 + u) * 2 + half], a, bh[u][half * 2], bh[u][half * 2 + 1]);
#pragma unroll
                    for (int u = 0; u < 2; ++u)
#pragma unroll
                        for (int half = 0; half < 2; ++half)
                            MMAF16(sacc[(p * 2 + u) * 2 + half], a, bl[u][half * 2], bl[u][half * 2 + 1]);
                }
            }
            const bool needMask = (kt * 64 + 63) > rbase;
#pragma unroll
            for (int j = 0; j < 8; ++j)
#pragma unroll
                for (int e = 0; e < 4; ++e) {
                    float v = sacc[j][e] * SCALE;
                    if (needMask) {
                        int rg = rbase + q4 + (e >> 1) * 8;
                        int kg = kt * 64 + j * 8 + l4 * 2 + (e & 1);
                        if (kg > rg) v = -1e30f;
                    }
                    sacc[j][e] = v;
                }
            float mx0 = -1e30f, mx1 = -1e30f;
#pragma unroll
            for (int j = 0; j < 8; ++j) {
                mx0 = fmaxf(mx0, fmaxf(sacc[j][0], sacc[j][1]));
                mx1 = fmaxf(mx1, fmaxf(sacc[j][2], sacc[j][3]));
            }
            mx0 = fmaxf(mx0, __shfl_xor_sync(0xffffffffu, mx0, 1));
            mx0 = fmaxf(mx0, __shfl_xor_sync(0xffffffffu, mx0, 2));
            mx1 = fmaxf(mx1, __shfl_xor_sync(0xffffffffu, mx1, 1));
            mx1 = fmaxf(mx1, __shfl_xor_sync(0xffffffffu, mx1, 2));
            float nm0 = fmaxf(m0, mx0), nm1 = fmaxf(m1, mx1);
            float corr0 = fexp(m0 - nm0), corr1 = fexp(m1 - nm1);
            m0 = nm0; m1 = nm1;
            float s0 = 0.f, s1 = 0.f;
            uint32_t prow0 = sbase + OP + (warp_m * 16 + q4) * RSV + l4 * 4;
            uint32_t prow1 = prow0 + 8 * RSV;
#pragma unroll
            for (int j = 0; j < 8; ++j) {
                float p00 = fexp(sacc[j][0] - m0);
                float p01 = fexp(sacc[j][1] - m0);
                float p10 = fexp(sacc[j][2] - m1);
                float p11 = fexp(sacc[j][3] - m1);
                s0 += p00 + p01; s1 += p10 + p11;
                __half2 hp0 = __halves2half2(__float2half(p00), __float2half(p01));
                __half2 hp1 = __halves2half2(__float2half(p10), __float2half(p11));
                asm volatile("st.shared.b32 [%0], %1;" :: "r"(prow0 + j * 16), "r"(*(uint32_t*)&hp0));
                asm volatile("st.shared.b32 [%0], %1;" :: "r"(prow1 + j * 16), "r"(*(uint32_t*)&hp1));
            }
            s0 += __shfl_xor_sync(0xffffffffu, s0, 1);
            s0 += __shfl_xor_sync(0xffffffffu, s0, 2);
            s1 += __shfl_xor_sync(0xffffffffu, s1, 1);
            s1 += __shfl_xor_sync(0xffffffffu, s1, 2);
            l0 = l0 * corr0 + s0;
            l1 = l1 * corr1 + s1;
#pragma unroll
            for (int f = 0; f < 16; ++f) {
                o[f][0] *= corr0; o[f][1] *= corr0;
                o[f][2] *= corr1; o[f][3] *= corr1;
            }
        }

        CPA_WAIT(0);
        __syncthreads();

        if (active) {
#pragma unroll
            for (int ks = 0; ks < 4; ++ks) {
                uint32_t pa[4];
                uint32_t raddr = sbase + OP + (warp_m * 16 + rowA) * RSV + ks * 32 + colA;
                LDSM4(pa, raddr);
#pragma unroll
                for (int p = 0; p < 4; ++p) {
                    uint32_t vb[2][4], vbl[2][4];
#pragma unroll
                    for (int u = 0; u < 2; ++u) {
                        uint32_t b0 = sbase + OVH + ((p * 2 + u) * 16 + rowB) * RSV + ks * 32 + colB;
                        LDSM4(vb[u], b0);
                        LDSM4(vbl[u], b0 + (OVL - OVH));
                    }
#pragma unroll
                    for (int u = 0; u < 2; ++u)
#pragma unroll
                        for (int half = 0; half < 2; ++half)
                            MMAF16(o[(p * 2 + u) * 2 + half], pa, vb[u][half * 2], vb[u][half * 2 + 1]);
#pragma unroll
                    for (int u = 0; u < 2; ++u)
#pragma unroll
                        for (int half = 0; half < 2; ++half)
                            MMAF16(o[(p * 2 + u) * 2 + half], pa, vbl[u][half * 2], vbl[u][half * 2 + 1]);
                }
            }
        }
    }

    float i0 = 1.f / l0, i1 = 1.f / l1;
    int row0 = qt * 128 + warp_m * 16 + q4;
#pragma unroll
    for (int f = 0; f < 16; ++f) {
        int col = ocol0 + f * 8 + l4 * 2;
        *(__half2*)(cs + (size_t)row0 * D_MODEL + col) =
            __halves2half2(__float2half(o[f][0] * i0), __float2half(o[f][1] * i0));
        *(__half2*)(cs + (size_t)(row0 + 8) * D_MODEL + col) =
            __halves2half2(__float2half(o[f][2] * i1), __float2half(o[f][3] * i1));
    }
}

// ---------------------------------------------------------------------------
extern "C" void kernel_launch(void* const* d_in, const int* in_sizes, int n_in,
                              void* d_out, int out_size) {
    const float* x  = (const float*)d_in[0];
    const float* Wq = (const float*)d_in[1];
    const float* Wk = (const float*)d_in[2];
    const float* Wv = (const float*)d_in[3];
    const float* Wo = (const float*)d_in[4];
    float* out = (float*)d_out;

    __half *xs, *cs, *qs, *kh, *kl, *vth, *vtl;
    __half *qth, *kth, *ktl, *vwh, *vwl, *oth;
    float2* tab;
    cudaGetSymbolAddress((void**)&xs, g_xs);
    cudaGetSymbolAddress((void**)&cs, g_cs);
    cudaGetSymbolAddress((void**)&qs, g_Qs);
    cudaGetSymbolAddress((void**)&kh, g_Kh);   cudaGetSymbolAddress((void**)&kl, g_Kl);
    cudaGetSymbolAddress((void**)&vth, g_Vth); cudaGetSymbolAddress((void**)&vtl, g_Vtl);
    cudaGetSymbolAddress((void**)&qth, g_WqTh);
    cudaGetSymbolAddress((void**)&kth, g_WkTh); cudaGetSymbolAddress((void**)&ktl, g_WkTl);
    cudaGetSymbolAddress((void**)&vwh, g_WvTh); cudaGetSymbolAddress((void**)&vwl, g_WvTl);
    cudaGetSymbolAddress((void**)&oth, g_WoTh);
    cudaGetSymbolAddress((void**)&tab, g_rope);

    cudaFuncSetAttribute(hgemm_qkv, cudaFuncAttributeMaxDynamicSharedMemorySize, GSMEM2);
    cudaFuncSetAttribute(hgemm_o,   cudaFuncAttributeMaxDynamicSharedMemorySize, GSMEM1);
    cudaFuncSetAttribute(flash_mma, cudaFuncAttributeMaxDynamicSharedMemorySize, FSMEM);

    prep_all<<<14848, 256>>>(x, Wq, Wk, Wv, Wo, xs, qth, kth, ktl,
                             vwh, vwl, oth, tab);
    hgemm_qkv<<<384, 256, GSMEM2>>>(xs, qth, kth, ktl, vwh, vwl,
                                    qs, kh, kl, vth, vtl, tab);
    flash_mma<<<dim3(N_TOK / 128, 16), 256, FSMEM>>>(qs, kh, kl, vth, vtl, cs);
    hgemm_o<<<dim3(16, 16), 256, GSMEM1>>>(cs, oth, out);

    (void)in_sizes; (void)n_in; (void)out_size;
}

// round 11
// speedup vs baseline: 1.9121x; 1.1101x over previous
#include <cuda_runtime.h>
#include <cuda_fp16.h>
#include <math.h>
#include <stdint.h>

#define N_TOK   2048
#define D_MODEL 2048
#define KV_D    512

// ---------------- scratch ---------------------------------------------------
__device__ __half g_xs[N_TOK * D_MODEL];
__device__ __half g_cs[N_TOK * D_MODEL];
__device__ __half g_Qs[N_TOK * D_MODEL];
__device__ __half g_Kh[N_TOK * KV_D];
__device__ __half g_Kl[N_TOK * KV_D];
__device__ __half g_Vt[KV_D * N_TOK];             // V single fp16, [kv][d][n]
__device__ __half g_WqTh[D_MODEL * D_MODEL];
__device__ __half g_WkTh[KV_D * D_MODEL];
__device__ __half g_WkTl[KV_D * D_MODEL];
__device__ __half g_WvTh[KV_D * D_MODEL];
__device__ __half g_WvTl[KV_D * D_MODEL];
__device__ __half g_WoTh[D_MODEL * D_MODEL];
__device__ float2 g_rope[N_TOK * 64];

__device__ __forceinline__ uint32_t smem_u32(const void* p) {
    uint32_t a;
    asm("{ .reg .u64 t; cvta.to.shared.u64 t, %1; cvt.u32.u64 %0, t; }"
        : "=r"(a) : "l"(p));
    return a;
}

#define LDSM4(r, addr)                                                        \
    asm volatile("ldmatrix.sync.aligned.m8n8.x4.shared.b16 {%0,%1,%2,%3}, [%4];" \
                 : "=r"((r)[0]), "=r"((r)[1]), "=r"((r)[2]), "=r"((r)[3])     \
                 : "r"(addr))

#define MMAF16(d, a, b0, b1)                                                  \
    asm volatile("mma.sync.aligned.m16n8k16.row.col.f32.f16.f16.f32 "         \
                 "{%0,%1,%2,%3}, {%4,%5,%6,%7}, {%8,%9}, {%0,%1,%2,%3};"      \
                 : "+f"((d)[0]), "+f"((d)[1]), "+f"((d)[2]), "+f"((d)[3])     \
                 : "r"((a)[0]), "r"((a)[1]), "r"((a)[2]), "r"((a)[3]),        \
                   "r"(b0), "r"(b1))

__device__ __forceinline__ void cpa16(uint32_t dst, const void* src) {
    asm volatile("cp.async.cg.shared.global [%0], [%1], 16;" :: "r"(dst), "l"(src));
}
#define CPA_COMMIT asm volatile("cp.async.commit_group;" ::: "memory")
#define CPA_WAIT(n) asm volatile("cp.async.wait_group %0;" :: "n"(n) : "memory")

__device__ __forceinline__ float fexp(float x) {
    float t = x * 1.4426950408889634f;
    t = fmaxf(t, -126.0f);
    float n = floorf(t);
    float f = t - n;
    float p = 1.5403530393283621e-4f;
    p = fmaf(p, f, 1.3333558146428443e-3f);
    p = fmaf(p, f, 9.6181291076284772e-3f);
    p = fmaf(p, f, 5.5504108664821580e-2f);
    p = fmaf(p, f, 2.4022650695910071e-1f);
    p = fmaf(p, f, 6.9314718055994531e-1f);
    p = fmaf(p, f, 1.0f);
    return __int_as_float(((int)n + 127) << 23) * p;
}

__device__ __forceinline__ void hsplit2(float a, float b, __half2& h, __half2& l) {
    __half ha = __float2half(a), hb = __float2half(b);
    h = __halves2half2(ha, hb);
    l = __halves2half2(__float2half(a - __half2float(ha)),
                       __float2half(b - __half2float(hb)));
}

// ---------------------------------------------------------------------------
// Prep: x -> fp16 | Wq/Wv/Wo -> transposed single; Wk -> hi/lo | rope tab
// ---------------------------------------------------------------------------
__global__ void __launch_bounds__(256) prep_all(
    const float* __restrict__ x, const float* __restrict__ Wq,
    const float* __restrict__ Wk, const float* __restrict__ Wv,
    const float* __restrict__ Wo,
    __half* __restrict__ xs,
    __half* __restrict__ qth,
    __half* __restrict__ kth, __half* __restrict__ ktl,
    __half* __restrict__ vth, __half* __restrict__ vtl,
    __half* __restrict__ oth,
    float2* __restrict__ tab) {
    const int bid = blockIdx.x;
    const int tid = threadIdx.x;
    if (bid < 4096) {
        int i = (bid * 256 + tid) * 4;
        float4 v = *(const float4*)(x + i);
        __half2* p = (__half2*)(xs + i);
        p[0] = __halves2half2(__float2half(v.x), __float2half(v.y));
        p[1] = __halves2half2(__float2half(v.z), __float2half(v.w));
    } else if (bid < 14336) {
        __shared__ float t[32][33];
        int wb = bid - 4096;
        const float* in; __half *doh, *dol; int Ndim, nx, sid;
        if (wb < 4096)      { in = Wq; doh = qth; dol = 0;   Ndim = D_MODEL; nx = 64; sid = wb; }
        else if (wb < 5120) { in = Wk; doh = kth; dol = ktl; Ndim = KV_D;   nx = 16; sid = wb - 4096; }
        else if (wb < 6144) { in = Wv; doh = vth; dol = vtl; Ndim = KV_D;   nx = 16; sid = wb - 5120; }
        else                { in = Wo; doh = oth; dol = 0;   Ndim = D_MODEL; nx = 64; sid = wb - 6144; }
        int n0 = (sid % nx) * 32, k0 = (sid / nx) * 32;
        int tx = tid & 31, ty = tid >> 5;
#pragma unroll
        for (int i = 0; i < 4; ++i)
            t[ty + 8 * i][tx] = in[(size_t)(k0 + ty + 8 * i) * Ndim + n0 + tx];
        __syncthreads();
#pragma unroll
        for (int i = 0; i < 4; ++i) {
            int nl = ty + 8 * i;
            float v = t[tx][nl];
            __half h = __float2half(v);
            size_t o = (size_t)(n0 + nl) * D_MODEL + k0 + tx;
            doh[o] = h;
            if (dol) dol[o] = __float2half(v - __half2float(h));
        }
    } else {
        int idx = (bid - 14336) * 256 + tid;
        int t = idx >> 6, i = idx & 63;
        double inv = exp(-9.210340371976184 * ((double)i / 64.0));
        double ang = (double)t * inv;
        double k = floor(ang * 0.15915494309189535);
        float r = (float)(ang - k * 6.283185307179586);
        float s, c;
        sincosf(r, &s, &c);
        tab[idx] = make_float2(c, s);
    }
}

// ---------------------------------------------------------------------------
// cp.async 3-stage GEMM cores. BM=BN=128, BK=32, 256 threads.
// ---------------------------------------------------------------------------
#define GRS    80
#define GTB    (128 * GRS)
#define GSMEM1 (3 * 2 * GTB)     // 61440
#define GSMEM2 (3 * 3 * GTB)     // 92160

template <int NT>
__device__ __forceinline__ void gemm_issue(
    uint32_t sbase, int stride, int slot, int c, int K, int tid,
    const __half* const* bases) {
    uint32_t stage = sbase + slot * stride;
#pragma unroll
    for (int t = 0; t < NT; ++t) {
#pragma unroll
        for (int i = 0; i < 2; ++i) {
            int idx = tid + i * 256;
            int r = idx >> 2, cc = idx & 3;
            cpa16(stage + t * GTB + r * GRS + cc * 16,
                  (const char*)bases[t] + ((size_t)r * K + c * 32) * 2 + cc * 16);
        }
    }
}

template <bool TWOPASS>
__device__ __forceinline__ void gemm_core(
    const __half* __restrict__ pA,
    const __half* __restrict__ pBh, const __half* __restrict__ pBl,
    int K, uint32_t sbase, float acc[2][8][4]) {
    constexpr int NT = TWOPASS ? 3 : 2;
    constexpr int STRIDE = NT * GTB;
    const __half* bases[NT];
    bases[0] = pA; bases[1] = pBh;
    if (TWOPASS) bases[2] = pBl;

    const int tid = threadIdx.x;
    const int lane = tid & 31;
    const int wid = tid >> 5;
    const int warp_m = wid & 3;
    const int warp_n = wid >> 2;
    const int q = lane >> 3;
    const int rowA = (lane & 7) + (q & 1) * 8;
    const int colA = (q >> 1) * 16;
    const int rowB = (lane & 7) + (q >> 1) * 8;
    const int colB = (q & 1) * 16;

    const int NC = K / 32;
    gemm_issue<NT>(sbase, STRIDE, 0, 0, K, tid, bases);
    CPA_COMMIT;
    gemm_issue<NT>(sbase, STRIDE, 1, 1, K, tid, bases);
    CPA_COMMIT;

    int slot = 0;
    for (int c = 0; c < NC; ++c) {
        CPA_WAIT(1);
        __syncthreads();
        if (c + 2 < NC) {
            int ns = slot + 2;
            if (ns >= 3) ns -= 3;
            gemm_issue<NT>(sbase, STRIDE, ns, c + 2, K, tid, bases);
        }
        CPA_COMMIT;

        const uint32_t sb = sbase + slot * STRIDE;
#pragma unroll
        for (int ks = 0; ks < 2; ++ks) {
            uint32_t a[2][4], bh[4][4], bl[4][4];
#pragma unroll
            for (int im = 0; im < 2; ++im) {
                uint32_t ra = sb + (warp_m * 32 + im * 16 + rowA) * GRS + ks * 32 + colA;
                LDSM4(a[im], ra);
            }
#pragma unroll
            for (int ib = 0; ib < 4; ++ib) {
                uint32_t rb = sb + GTB + (warp_n * 64 + ib * 16 + rowB) * GRS + ks * 32 + colB;
                LDSM4(bh[ib], rb);
                if (TWOPASS) LDSM4(bl[ib], rb + GTB);
            }
#pragma unroll
            for (int im = 0; im < 2; ++im)
#pragma unroll
                for (int j = 0; j < 8; ++j) {
                    const int f = j >> 1, h = (j & 1) * 2;
                    MMAF16(acc[im][j], a[im], bh[f][h], bh[f][h + 1]);
                }
            if (TWOPASS) {
#pragma unroll
                for (int im = 0; im < 2; ++im)
#pragma unroll
                    for (int j = 0; j < 8; ++j) {
                        const int f = j >> 1, h = (j & 1) * 2;
                        MMAF16(acc[im][j], a[im], bl[f][h], bl[f][h + 1]);
                    }
            }
        }
        if (++slot == 3) slot = 0;
    }
}

// ---- fused Q+K+V projection (384 blocks; long 2-pass K blocks first) ------
__global__ void __launch_bounds__(256) hgemm_qkv(
    const __half* __restrict__ A,
    const __half* __restrict__ QBh,
    const __half* __restrict__ KBh, const __half* __restrict__ KBl,
    const __half* __restrict__ VBh, const __half* __restrict__ VBl,
    __half* __restrict__ qs,
    __half* __restrict__ kh, __half* __restrict__ kl,
    __half* __restrict__ vt,
    const float2* __restrict__ tab) {
    extern __shared__ char smem[];
    const uint32_t sbase = smem_u32(smem);
    const int bid = blockIdx.x;
    const int K = D_MODEL;
    int kind, m0, n0;
    if (bid < 64)       { kind = 1; m0 = (bid >> 2) * 128; n0 = (bid & 3) * 128; }      // K (2-pass)
    else if (bid < 128) { int s = bid - 64; kind = 2; m0 = (s >> 2) * 128; n0 = (s & 3) * 128; }  // V (2-pass)
    else                { int s = bid - 128; kind = 0; m0 = (s >> 4) * 128; n0 = (s & 15) * 128; } // Q (1-pass)

    float acc[2][8][4];
#pragma unroll
    for (int im = 0; im < 2; ++im)
#pragma unroll
        for (int j = 0; j < 8; ++j)
#pragma unroll
            for (int e = 0; e < 4; ++e) acc[im][j][e] = 0.f;

    if (kind == 0) {
        gemm_core<false>(A + (size_t)m0 * K, QBh + (size_t)n0 * K, 0, K, sbase, acc);
    } else if (kind == 1) {
        gemm_core<true>(A + (size_t)m0 * K, KBh + (size_t)n0 * K,
                        KBl + (size_t)n0 * K, K, sbase, acc);
    } else {
        gemm_core<true>(A + (size_t)m0 * K, VBh + (size_t)n0 * K,
                        VBl + (size_t)n0 * K, K, sbase, acc);
    }

    const int tid = threadIdx.x;
    const int lane = tid & 31, wid = tid >> 5;
    const int q4 = lane >> 2, l4 = lane & 3;
    if (kind == 0) {
#pragma unroll
        for (int im = 0; im < 2; ++im)
#pragma unroll
            for (int j = 0; j < 8; ++j) {
                int row = m0 + (wid & 3) * 32 + im * 16 + q4;
                int col = n0 + (wid >> 2) * 64 + j * 8 + l4 * 2;
#pragma unroll
                for (int rr = 0; rr < 2; ++rr) {
                    int r = row + rr * 8;
                    float v0 = acc[im][j][rr * 2], v1 = acc[im][j][rr * 2 + 1];
                    float2 cs = tab[r * 64 + ((col & 127) >> 1)];
                    float oe = v0 * cs.x - v1 * cs.y;
                    float oo = v0 * cs.y + v1 * cs.x;
                    *(__half2*)(qs + (size_t)r * D_MODEL + col) =
                        __halves2half2(__float2half(oe), __float2half(oo));
                }
            }
    } else if (kind == 1) {
#pragma unroll
        for (int im = 0; im < 2; ++im)
#pragma unroll
            for (int j = 0; j < 8; ++j) {
                int row = m0 + (wid & 3) * 32 + im * 16 + q4;
                int col = n0 + (wid >> 2) * 64 + j * 8 + l4 * 2;
#pragma unroll
                for (int rr = 0; rr < 2; ++rr) {
                    int r = row + rr * 8;
                    float v0 = acc[im][j][rr * 2], v1 = acc[im][j][rr * 2 + 1];
                    float2 cs = tab[r * 64 + ((col & 127) >> 1)];
                    float oe = v0 * cs.x - v1 * cs.y;
                    float oo = v0 * cs.y + v1 * cs.x;
                    __half2 h, l;
                    hsplit2(oe, oo, h, l);
                    *(__half2*)(kh + (size_t)r * KV_D + col) = h;
                    *(__half2*)(kl + (size_t)r * KV_D + col) = l;
                }
            }
    } else {
        __syncthreads();
        float* tS = (float*)smem;  // [128][132]
#pragma unroll
        for (int im = 0; im < 2; ++im)
#pragma unroll
            for (int j = 0; j < 8; ++j) {
                int r = (wid & 3) * 32 + im * 16 + q4;
                int cl = (wid >> 2) * 64 + j * 8 + l4 * 2;
                tS[cl * 132 + r] = acc[im][j][0];
                tS[(cl + 1) * 132 + r] = acc[im][j][1];
                tS[cl * 132 + r + 8] = acc[im][j][2];
                tS[(cl + 1) * 132 + r + 8] = acc[im][j][3];
            }
        __syncthreads();
        const int dkv = n0 >> 7;
        const int d = tid >> 1, half = (tid & 1) * 64;
        size_t dst = (size_t)dkv * 128 * N_TOK + (size_t)d * N_TOK + m0 + half;
#pragma unroll
        for (int k = 0; k < 64; k += 2) {
            *(__half2*)(vt + dst + k) =
                __halves2half2(__float2half(tS[d * 132 + half + k]),
                               __float2half(tS[d * 132 + half + k + 1]));
        }
    }
}

// ---- output projection: single-pass ---------------------------------------
__global__ void __launch_bounds__(256) hgemm_o(
    const __half* __restrict__ A, const __half* __restrict__ Bh,
    float* __restrict__ C) {
    extern __shared__ char smem[];
    const uint32_t sbase = smem_u32(smem);
    const int m0 = blockIdx.y * 128, n0 = blockIdx.x * 128;
    const int K = D_MODEL, N = D_MODEL;
    float acc[2][8][4];
#pragma unroll
    for (int im = 0; im < 2; ++im)
#pragma unroll
        for (int j = 0; j < 8; ++j)
#pragma unroll
            for (int e = 0; e < 4; ++e) acc[im][j][e] = 0.f;
    gemm_core<false>(A + (size_t)m0 * K, Bh + (size_t)n0 * K, 0, K, sbase, acc);
    const int lane = threadIdx.x & 31, wid = threadIdx.x >> 5;
#pragma unroll
    for (int im = 0; im < 2; ++im)
#pragma unroll
        for (int j = 0; j < 8; ++j) {
            int row = m0 + (wid & 3) * 32 + im * 16 + (lane >> 2);
            int col = n0 + (wid >> 2) * 64 + j * 8 + (lane & 3) * 2;
            *(float2*)(C + (size_t)row * N + col) = make_float2(acc[im][j][0], acc[im][j][1]);
            *(float2*)(C + (size_t)(row + 8) * N + col) = make_float2(acc[im][j][2], acc[im][j][3]);
        }
}

// ---------------------------------------------------------------------------
// Flash attention: Q single resident, K hi/lo double-buffered, V single
// pipelined, P single, PV single-pass.
// ---------------------------------------------------------------------------
#define RSQ 272
#define RSV 144
#define OQ    0                  // 128*272 = 34816
#define OKST  34816              // 2 stages * 34816 (Kh +0, Kl +17408)
#define OV    104448             // 128*144 = 18432
#define OP    122880             // 128*144 = 18432
#define FSMEM 141312

__global__ void __launch_bounds__(256, 1) flash_mma(
    const __half* __restrict__ Qs,
    const __half* __restrict__ Kh, const __half* __restrict__ Kl,
    const __half* __restrict__ Vt,
    __half* __restrict__ cs) {
    const int qt = gridDim.x - 1 - blockIdx.x;
    const int h  = blockIdx.y;
    const int g  = h >> 2, kv = h & 3;
    const int qcol0 = g * 512 + kv * 128;
    const int kcol0 = kv * 128;
    const int ocol0 = (kv * 4 + g) * 128;
    const __half* vp = Vt + (size_t)kv * 128 * N_TOK;

    extern __shared__ char smem[];
    const uint32_t sbase = smem_u32(smem);

    const int tid = threadIdx.x;
    const int lane = tid & 31;
    const int warp_m = tid >> 5;
    const int q4 = lane >> 2, l4 = lane & 3;
    const int qq = lane >> 3;
    const int rowA = (lane & 7) + (qq & 1) * 8;
    const int colA = (qq >> 1) * 16;
    const int rowB = (lane & 7) + (qq >> 1) * 8;
    const int colB = (qq & 1) * 16;
    const float SCALE = 0.08838834764831845f;

#pragma unroll
    for (int i = 0; i < 8; ++i) {
        int idx = tid + i * 256;
        int r = idx >> 4, c = idx & 15;
        size_t go = (size_t)(qt * 128 + r) * D_MODEL + qcol0 + c * 8;
        *(uint4*)(smem + OQ + r * RSQ + c * 16) = *(const uint4*)(Qs + go);
    }

    {
#pragma unroll
        for (int i = 0; i < 8; ++i) {
            int idx = tid + i * 256;
            int half = i >> 2;
            int li = idx & 1023;
            int r = li >> 4, c = li & 15;
            const __half* src = half ? Kl : Kh;
            cpa16(sbase + OKST + half * 17408 + r * RSQ + c * 16,
                  src + (size_t)r * KV_D + kcol0 + c * 8);
        }
        CPA_COMMIT;
    }

    float o[16][4];
#pragma unroll
    for (int f = 0; f < 16; ++f)
#pragma unroll
        for (int e = 0; e < 4; ++e) o[f][e] = 0.f;
    float m0 = -1e30f, m1 = -1e30f, l0 = 0.f, l1 = 0.f;

    const int nkt = 2 * qt + 2;
    for (int kt = 0; kt < nkt; ++kt) {
        __syncthreads();

        // issue V(kt) (single) and K(kt+1) (hi/lo)
#pragma unroll
        for (int i = 0; i < 4; ++i) {
            int idx = tid + i * 256;
            int r = idx >> 3, c = idx & 7;
            cpa16(sbase + OV + r * RSV + c * 16,
                  vp + (size_t)r * N_TOK + kt * 64 + c * 8);
        }
        if (kt + 1 < nkt) {
            uint32_t kst = sbase + OKST + ((kt + 1) & 1) * 34816;
#pragma unroll
            for (int i = 0; i < 8; ++i) {
                int idx = tid + i * 256;
                int half = i >> 2;
                int li = idx & 1023;
                int r = li >> 4, c = li & 15;
                const __half* src = half ? Kl : Kh;
                cpa16(kst + half * 17408 + r * RSQ + c * 16,
                      src + (size_t)((kt + 1) * 64 + r) * KV_D + kcol0 + c * 8);
            }
        }
        CPA_COMMIT;

        CPA_WAIT(1);
        __syncthreads();

        const int rbase = qt * 128 + warp_m * 16;
        const bool active = (kt * 64) <= (rbase + 15);
        const uint32_t kst = sbase + OKST + (kt & 1) * 34816;

        if (active) {
            float sacc[8][4];
#pragma unroll
            for (int j = 0; j < 8; ++j)
#pragma unroll
                for (int e = 0; e < 4; ++e) sacc[j][e] = 0.f;
#pragma unroll
            for (int ks = 0; ks < 8; ++ks) {
                uint32_t a[4];
                uint32_t ra = sbase + OQ + (warp_m * 16 + rowA) * RSQ + ks * 32 + colA;
                LDSM4(a, ra);
#pragma unroll
                for (int p = 0; p < 2; ++p) {
                    uint32_t bh[2][4], bl[2][4];
#pragma unroll
                    for (int u = 0; u < 2; ++u) {
                        uint32_t rb = kst + ((p * 2 + u) * 16 + rowB) * RSQ + ks * 32 + colB;
                        LDSM4(bh[u], rb);
                        LDSM4(bl[u], rb + 17408);
                    }
#pragma unroll
                    for (int u = 0; u < 2; ++u)
#pragma unroll
                        for (int half = 0; half < 2; ++half)
                            MMAF16(sacc[(p * 2 + u) * 2 + half], a, bh[u][half * 2], bh[u][half * 2 + 1]);
#pragma unroll
                    for (int u = 0; u < 2; ++u)
#pragma unroll
                        for (int half = 0; half < 2; ++half)
                            MMAF16(sacc[(p * 2 + u) * 2 + half], a, bl[u][half * 2], bl[u][half * 2 + 1]);
                }
            }
            const bool needMask = (kt * 64 + 63) > rbase;
#pragma unroll
            for (int j = 0; j < 8; ++j)
#pragma unroll
                for (int e = 0; e < 4; ++e) {
                    float v = sacc[j][e] * SCALE;
                    if (needMask) {
                        int rg = rbase + q4 + (e >> 1) * 8;
                        int kg = kt * 64 + j * 8 + l4 * 2 + (e & 1);
                        if (kg > rg) v = -1e30f;
                    }
                    sacc[j][e] = v;
                }
            float mx0 = -1e30f, mx1 = -1e30f;
#pragma unroll
            for (int j = 0; j < 8; ++j) {
                mx0 = fmaxf(mx0, fmaxf(sacc[j][0], sacc[j][1]));
                mx1 = fmaxf(mx1, fmaxf(sacc[j][2], sacc[j][3]));
            }
            mx0 = fmaxf(mx0, __shfl_xor_sync(0xffffffffu, mx0, 1));
            mx0 = fmaxf(mx0, __shfl_xor_sync(0xffffffffu, mx0, 2));
            mx1 = fmaxf(mx1, __shfl_xor_sync(0xffffffffu, mx1, 1));
            mx1 = fmaxf(mx1, __shfl_xor_sync(0xffffffffu, mx1, 2));
            float nm0 = fmaxf(m0, mx0), nm1 = fmaxf(m1, mx1);
            float corr0 = fexp(m0 - nm0), corr1 = fexp(m1 - nm1);
            m0 = nm0; m1 = nm1;
            float s0 = 0.f, s1 = 0.f;
            uint32_t prow0 = sbase + OP + (warp_m * 16 + q4) * RSV + l4 * 4;
            uint32_t prow1 = prow0 + 8 * RSV;
#pragma unroll
            for (int j = 0; j < 8; ++j) {
                float p00 = fexp(sacc[j][0] - m0);
                float p01 = fexp(sacc[j][1] - m0);
                float p10 = fexp(sacc[j][2] - m1);
                float p11 = fexp(sacc[j][3] - m1);
                s0 += p00 + p01; s1 += p10 + p11;
                __half2 hp0 = __halves2half2(__float2half(p00), __float2half(p01));
                __half2 hp1 = __halves2half2(__float2half(p10), __float2half(p11));
                asm volatile("st.shared.b32 [%0], %1;" :: "r"(prow0 + j * 16), "r"(*(uint32_t*)&hp0));
                asm volatile("st.shared.b32 [%0], %1;" :: "r"(prow1 + j * 16), "r"(*(uint32_t*)&hp1));
            }
            s0 += __shfl_xor_sync(0xffffffffu, s0, 1);
            s0 += __shfl_xor_sync(0xffffffffu, s0, 2);
            s1 += __shfl_xor_sync(0xffffffffu, s1, 1);
            s1 += __shfl_xor_sync(0xffffffffu, s1, 2);
            l0 = l0 * corr0 + s0;
            l1 = l1 * corr1 + s1;
#pragma unroll
            for (int f = 0; f < 16; ++f) {
                o[f][0] *= corr0; o[f][1] *= corr0;
                o[f][2] *= corr1; o[f][3] *= corr1;
            }
        }

        CPA_WAIT(0);
        __syncthreads();

        if (active) {
#pragma unroll
            for (int ks = 0; ks < 4; ++ks) {
                uint32_t pa[4];
                uint32_t raddr = sbase + OP + (warp_m * 16 + rowA) * RSV + ks * 32 + colA;
                LDSM4(pa, raddr);
#pragma unroll
                for (int p = 0; p < 4; ++p) {
                    uint32_t vb[2][4];
#pragma unroll
                    for (int u = 0; u < 2; ++u) {
                        uint32_t b0 = sbase + OV + ((p * 2 + u) * 16 + rowB) * RSV + ks * 32 + colB;
                        LDSM4(vb[u], b0);
                    }
#pragma unroll
                    for (int u = 0; u < 2; ++u)
#pragma unroll
                        for (int half = 0; half < 2; ++half)
                            MMAF16(o[(p * 2 + u) * 2 + half], pa, vb[u][half * 2], vb[u][half * 2 + 1]);
                }
            }
        }
    }

    float i0 = 1.f / l0, i1 = 1.f / l1;
    int row0 = qt * 128 + warp_m * 16 + q4;
#pragma unroll
    for (int f = 0; f < 16; ++f) {
        int col = ocol0 + f * 8 + l4 * 2;
        *(__half2*)(cs + (size_t)row0 * D_MODEL + col) =
            __halves2half2(__float2half(o[f][0] * i0), __float2half(o[f][1] * i0));
        *(__half2*)(cs + (size_t)(row0 + 8) * D_MODEL + col) =
            __halves2half2(__float2half(o[f][2] * i1), __float2half(o[f][3] * i1));
    }
}

// ---------------------------------------------------------------------------
extern "C" void kernel_launch(void* const* d_in, const int* in_sizes, int n_in,
                              void* d_out, int out_size) {
    const float* x  = (const float*)d_in[0];
    const float* Wq = (const float*)d_in[1];
    const float* Wk = (const float*)d_in[2];
    const float* Wv = (const float*)d_in[3];
    const float* Wo = (const float*)d_in[4];
    float* out = (float*)d_out;

    __half *xs, *cs, *qs, *kh, *kl, *vt;
    __half *qth, *kth, *ktl, *vwh, *vwl, *oth;
    float2* tab;
    cudaGetSymbolAddress((void**)&xs, g_xs);
    cudaGetSymbolAddress((void**)&cs, g_cs);
    cudaGetSymbolAddress((void**)&qs, g_Qs);
    cudaGetSymbolAddress((void**)&kh, g_Kh);   cudaGetSymbolAddress((void**)&kl, g_Kl);
    cudaGetSymbolAddress((void**)&vt, g_Vt);
    cudaGetSymbolAddress((void**)&qth, g_WqTh);
    cudaGetSymbolAddress((void**)&kth, g_WkTh); cudaGetSymbolAddress((void**)&ktl, g_WkTl);
    cudaGetSymbolAddress((void**)&vwh, g_WvTh); cudaGetSymbolAddress((void**)&vwl, g_WvTl);
    cudaGetSymbolAddress((void**)&oth, g_WoTh);
    cudaGetSymbolAddress((void**)&tab, g_rope);

    cudaFuncSetAttribute(hgemm_qkv, cudaFuncAttributeMaxDynamicSharedMemorySize, GSMEM2);
    cudaFuncSetAttribute(hgemm_o,   cudaFuncAttributeMaxDynamicSharedMemorySize, GSMEM1);
    cudaFuncSetAttribute(flash_mma, cudaFuncAttributeMaxDynamicSharedMemorySize, FSMEM);

    prep_all<<<14848, 256>>>(x, Wq, Wk, Wv, Wo, xs, qth, kth, ktl,
                             vwh, vwl, oth, tab);
    hgemm_qkv<<<384, 256, GSMEM2>>>(xs, qth, kth, ktl, vwh, vwl,
                                    qs, kh, kl, vt, tab);
    flash_mma<<<dim3(N_TOK / 128, 16), 256, FSMEM>>>(qs, kh, kl, vt, cs);
    hgemm_o<<<dim3(16, 16), 256, GSMEM1>>>(cs, oth, out);

    (void)in_sizes; (void)n_in; (void)out_size;
}

// round 14
// speedup vs baseline: 2.1643x; 1.1319x over previous
#include <cuda_runtime.h>
#include <cuda_fp16.h>
#include <math.h>
#include <stdint.h>

#define N_TOK   2048
#define D_MODEL 2048
#define KV_D    512

// ---------------- scratch ---------------------------------------------------
__device__ __half g_xs[N_TOK * D_MODEL];
__device__ __half g_cs[N_TOK * D_MODEL];
__device__ __half g_Qs[N_TOK * D_MODEL];
__device__ __half g_Ks[N_TOK * KV_D];
__device__ __half g_Vt[KV_D * N_TOK];             // [kv][d][n]
__device__ __half g_WqT[D_MODEL * D_MODEL];
__device__ __half g_WkT[KV_D * D_MODEL];
__device__ __half g_WvT[KV_D * D_MODEL];
__device__ __half g_WoT[D_MODEL * D_MODEL];
__device__ float2 g_rope[N_TOK * 64];

__device__ __forceinline__ uint32_t smem_u32(const void* p) {
    uint32_t a;
    asm("{ .reg .u64 t; cvta.to.shared.u64 t, %1; cvt.u32.u64 %0, t; }"
        : "=r"(a) : "l"(p));
    return a;
}

#define LDSM4(r, addr)                                                        \
    asm volatile("ldmatrix.sync.aligned.m8n8.x4.shared.b16 {%0,%1,%2,%3}, [%4];" \
                 : "=r"((r)[0]), "=r"((r)[1]), "=r"((r)[2]), "=r"((r)[3])     \
                 : "r"(addr))

#define MMAF16(d, a, b0, b1)                                                  \
    asm volatile("mma.sync.aligned.m16n8k16.row.col.f32.f16.f16.f32 "         \
                 "{%0,%1,%2,%3}, {%4,%5,%6,%7}, {%8,%9}, {%0,%1,%2,%3};"      \
                 : "+f"((d)[0]), "+f"((d)[1]), "+f"((d)[2]), "+f"((d)[3])     \
                 : "r"((a)[0]), "r"((a)[1]), "r"((a)[2]), "r"((a)[3]),        \
                   "r"(b0), "r"(b1))

__device__ __forceinline__ void cpa16(uint32_t dst, const void* src) {
    asm volatile("cp.async.cg.shared.global [%0], [%1], 16;" :: "r"(dst), "l"(src));
}
#define CPA_COMMIT asm volatile("cp.async.commit_group;" ::: "memory")
#define CPA_WAIT(n) asm volatile("cp.async.wait_group %0;" :: "n"(n) : "memory")

__device__ __forceinline__ float fexp(float x) {
    float t = x * 1.4426950408889634f;
    t = fmaxf(t, -126.0f);
    float n = floorf(t);
    float f = t - n;
    float p = 1.5403530393283621e-4f;
    p = fmaf(p, f, 1.3333558146428443e-3f);
    p = fmaf(p, f, 9.6181291076284772e-3f);
    p = fmaf(p, f, 5.5504108664821580e-2f);
    p = fmaf(p, f, 2.4022650695910071e-1f);
    p = fmaf(p, f, 6.9314718055994531e-1f);
    p = fmaf(p, f, 1.0f);
    return __int_as_float(((int)n + 127) << 23) * p;
}

// ---------------------------------------------------------------------------
// Prep: x -> fp16 | all weights -> transposed fp16 single | rope table
// ---------------------------------------------------------------------------
__global__ void __launch_bounds__(256) prep_all(
    const float* __restrict__ x, const float* __restrict__ Wq,
    const float* __restrict__ Wk, const float* __restrict__ Wv,
    const float* __restrict__ Wo,
    __half* __restrict__ xs,
    __half* __restrict__ qt, __half* __restrict__ kt,
    __half* __restrict__ vt, __half* __restrict__ ot,
    float2* __restrict__ tab) {
    const int bid = blockIdx.x;
    const int tid = threadIdx.x;
    if (bid < 4096) {
        int i = (bid * 256 + tid) * 4;
        float4 v = *(const float4*)(x + i);
        __half2* p = (__half2*)(xs + i);
        p[0] = __halves2half2(__float2half(v.x), __float2half(v.y));
        p[1] = __halves2half2(__float2half(v.z), __float2half(v.w));
    } else if (bid < 14336) {
        __shared__ float t[32][33];
        int wb = bid - 4096;
        const float* in; __half* doh; int Ndim, nx, sid;
        if (wb < 4096)      { in = Wq; doh = qt; Ndim = D_MODEL; nx = 64; sid = wb; }
        else if (wb < 5120) { in = Wk; doh = kt; Ndim = KV_D;   nx = 16; sid = wb - 4096; }
        else if (wb < 6144) { in = Wv; doh = vt; Ndim = KV_D;   nx = 16; sid = wb - 5120; }
        else                { in = Wo; doh = ot; Ndim = D_MODEL; nx = 64; sid = wb - 6144; }
        int n0 = (sid % nx) * 32, k0 = (sid / nx) * 32;
        int tx = tid & 31, ty = tid >> 5;
#pragma unroll
        for (int i = 0; i < 4; ++i)
            t[ty + 8 * i][tx] = in[(size_t)(k0 + ty + 8 * i) * Ndim + n0 + tx];
        __syncthreads();
#pragma unroll
        for (int i = 0; i < 4; ++i) {
            int nl = ty + 8 * i;
            doh[(size_t)(n0 + nl) * D_MODEL + k0 + tx] = __float2half(t[tx][nl]);
        }
    } else {
        int idx = (bid - 14336) * 256 + tid;
        int t = idx >> 6, i = idx & 63;
        double inv = exp(-9.210340371976184 * ((double)i / 64.0));
        double ang = (double)t * inv;
        double k = floor(ang * 0.15915494309189535);
        float r = (float)(ang - k * 6.283185307179586);
        float s, c;
        sincosf(r, &s, &c);
        tab[idx] = make_float2(c, s);
    }
}

// ---------------------------------------------------------------------------
// cp.async 3-stage single-pass fp16 GEMM core. BM=BN=128, BK=32, 256 threads.
// ---------------------------------------------------------------------------
#define GRS    80
#define GTB    (128 * GRS)
#define GSTRIDE (2 * GTB)
#define GSMEM  (3 * GSTRIDE)     // 61440 (mainloop)
#define QKV_SMEM 69632           // max(mainloop 61440, V-transpose epi 67584)

__device__ __forceinline__ void gemm_issue(
    uint32_t sbase, int slot, int c, int K, int tid,
    const __half* pA, const __half* pB) {
    uint32_t stage = sbase + slot * GSTRIDE;
    const __half* bases[2] = {pA, pB};
#pragma unroll
    for (int t = 0; t < 2; ++t) {
#pragma unroll
        for (int i = 0; i < 2; ++i) {
            int idx = tid + i * 256;
            int r = idx >> 2, cc = idx & 3;
            cpa16(stage + t * GTB + r * GRS + cc * 16,
                  (const char*)bases[t] + ((size_t)r * K + c * 32) * 2 + cc * 16);
        }
    }
}

__device__ __forceinline__ void gemm_core(
    const __half* __restrict__ pA, const __half* __restrict__ pB,
    int K, uint32_t sbase, float acc[2][8][4]) {
    const int tid = threadIdx.x;
    const int lane = tid & 31;
    const int wid = tid >> 5;
    const int warp_m = wid & 3;
    const int warp_n = wid >> 2;
    const int q = lane >> 3;
    const int rowA = (lane & 7) + (q & 1) * 8;
    const int colA = (q >> 1) * 16;
    const int rowB = (lane & 7) + (q >> 1) * 8;
    const int colB = (q & 1) * 16;

    const int NC = K / 32;
    gemm_issue(sbase, 0, 0, K, tid, pA, pB);
    CPA_COMMIT;
    gemm_issue(sbase, 1, 1, K, tid, pA, pB);
    CPA_COMMIT;

    int slot = 0;
    for (int c = 0; c < NC; ++c) {
        CPA_WAIT(1);
        __syncthreads();
        if (c + 2 < NC) {
            int ns = slot + 2;
            if (ns >= 3) ns -= 3;
            gemm_issue(sbase, ns, c + 2, K, tid, pA, pB);
        }
        CPA_COMMIT;

        const uint32_t sb = sbase + slot * GSTRIDE;
#pragma unroll
        for (int ks = 0; ks < 2; ++ks) {
            uint32_t a[2][4], b[4][4];
#pragma unroll
            for (int im = 0; im < 2; ++im) {
                uint32_t ra = sb + (warp_m * 32 + im * 16 + rowA) * GRS + ks * 32 + colA;
                LDSM4(a[im], ra);
            }
#pragma unroll
            for (int ib = 0; ib < 4; ++ib) {
                uint32_t rb = sb + GTB + (warp_n * 64 + ib * 16 + rowB) * GRS + ks * 32 + colB;
                LDSM4(b[ib], rb);
            }
#pragma unroll
            for (int im = 0; im < 2; ++im)
#pragma unroll
                for (int j = 0; j < 8; ++j) {
                    const int f = j >> 1, h = (j & 1) * 2;
                    MMAF16(acc[im][j], a[im], b[f][h], b[f][h + 1]);
                }
        }
        if (++slot == 3) slot = 0;
    }
}

// ---- fused Q+K+V projection (384 uniform 1-pass blocks) -------------------
__global__ void __launch_bounds__(256) hgemm_qkv(
    const __half* __restrict__ A,
    const __half* __restrict__ QB, const __half* __restrict__ KB,
    const __half* __restrict__ VB,
    __half* __restrict__ qs, __half* __restrict__ ks, __half* __restrict__ vt,
    const float2* __restrict__ tab) {
    extern __shared__ char smem[];
    const uint32_t sbase = smem_u32(smem);
    const int bid = blockIdx.x;
    const int K = D_MODEL;
    int kind, m0, n0;
    const __half* B;
    if (bid < 64)       { kind = 1; m0 = (bid >> 2) * 128; n0 = (bid & 3) * 128; B = KB; }
    else if (bid < 128) { int s = bid - 64; kind = 2; m0 = (s >> 2) * 128; n0 = (s & 3) * 128; B = VB; }
    else                { int s = bid - 128; kind = 0; m0 = (s >> 4) * 128; n0 = (s & 15) * 128; B = QB; }

    float acc[2][8][4];
#pragma unroll
    for (int im = 0; im < 2; ++im)
#pragma unroll
        for (int j = 0; j < 8; ++j)
#pragma unroll
            for (int e = 0; e < 4; ++e) acc[im][j][e] = 0.f;
    gemm_core(A + (size_t)m0 * K, B + (size_t)n0 * K, K, sbase, acc);

    const int tid = threadIdx.x;
    const int lane = tid & 31, wid = tid >> 5;
    const int q4 = lane >> 2, l4 = lane & 3;
    if (kind != 2) {
        // Q or K: rope + store single fp16
        const int N = (kind == 0) ? D_MODEL : KV_D;
        __half* dst = (kind == 0) ? qs : ks;
#pragma unroll
        for (int im = 0; im < 2; ++im)
#pragma unroll
            for (int j = 0; j < 8; ++j) {
                int row = m0 + (wid & 3) * 32 + im * 16 + q4;
                int col = n0 + (wid >> 2) * 64 + j * 8 + l4 * 2;
#pragma unroll
                for (int rr = 0; rr < 2; ++rr) {
                    int r = row + rr * 8;
                    float v0 = acc[im][j][rr * 2], v1 = acc[im][j][rr * 2 + 1];
                    float2 cs = tab[r * 64 + ((col & 127) >> 1)];
                    float oe = v0 * cs.x - v1 * cs.y;
                    float oo = v0 * cs.y + v1 * cs.x;
                    *(__half2*)(dst + (size_t)r * N + col) =
                        __halves2half2(__float2half(oe), __float2half(oo));
                }
            }
    } else {
        // V: transpose via smem (128*132*4 = 67584 B <= QKV_SMEM)
        __syncthreads();
        float* tS = (float*)smem;  // [128][132]
#pragma unroll
        for (int im = 0; im < 2; ++im)
#pragma unroll
            for (int j = 0; j < 8; ++j) {
                int r = (wid & 3) * 32 + im * 16 + q4;
                int cl = (wid >> 2) * 64 + j * 8 + l4 * 2;
                tS[cl * 132 + r] = acc[im][j][0];
                tS[(cl + 1) * 132 + r] = acc[im][j][1];
                tS[cl * 132 + r + 8] = acc[im][j][2];
                tS[(cl + 1) * 132 + r + 8] = acc[im][j][3];
            }
        __syncthreads();
        const int dkv = n0 >> 7;
        const int d = tid >> 1, half = (tid & 1) * 64;
        size_t dst = (size_t)dkv * 128 * N_TOK + (size_t)d * N_TOK + m0 + half;
#pragma unroll
        for (int k = 0; k < 64; k += 2) {
            *(__half2*)(vt + dst + k) =
                __halves2half2(__float2half(tS[d * 132 + half + k]),
                               __float2half(tS[d * 132 + half + k + 1]));
        }
    }
}

// ---- output projection ----------------------------------------------------
__global__ void __launch_bounds__(256) hgemm_o(
    const __half* __restrict__ A, const __half* __restrict__ B,
    float* __restrict__ C) {
    extern __shared__ char smem[];
    const uint32_t sbase = smem_u32(smem);
    const int m0 = blockIdx.y * 128, n0 = blockIdx.x * 128;
    const int K = D_MODEL, N = D_MODEL;
    float acc[2][8][4];
#pragma unroll
    for (int im = 0; im < 2; ++im)
#pragma unroll
        for (int j = 0; j < 8; ++j)
#pragma unroll
            for (int e = 0; e < 4; ++e) acc[im][j][e] = 0.f;
    gemm_core(A + (size_t)m0 * K, B + (size_t)n0 * K, K, sbase, acc);
    const int lane = threadIdx.x & 31, wid = threadIdx.x >> 5;
#pragma unroll
    for (int im = 0; im < 2; ++im)
#pragma unroll
        for (int j = 0; j < 8; ++j) {
            int row = m0 + (wid & 3) * 32 + im * 16 + (lane >> 2);
            int col = n0 + (wid >> 2) * 64 + j * 8 + (lane & 3) * 2;
            *(float2*)(C + (size_t)row * N + col) = make_float2(acc[im][j][0], acc[im][j][1]);
            *(float2*)(C + (size_t)(row + 8) * N + col) = make_float2(acc[im][j][2], acc[im][j][3]);
        }
}

// ---------------------------------------------------------------------------
// Flash attention: all single fp16. Q resident, K double-buffered cp.async,
// V pipelined, P single, single-pass MMAs throughout.
// ---------------------------------------------------------------------------
#define RSQ 272
#define RSV 144
#define OQ    0                  // 128*272 = 34816
#define OKST  34816              // 2 stages * 17408 (64*272)
#define OV    69632              // 128*144 = 18432
#define OP    88064              // 128*144 = 18432
#define FSMEM 106496

__global__ void __launch_bounds__(256, 1) flash_mma(
    const __half* __restrict__ Qs, const __half* __restrict__ Ks,
    const __half* __restrict__ Vt, __half* __restrict__ cs) {
    const int qt = gridDim.x - 1 - blockIdx.x;
    const int h  = blockIdx.y;
    const int g  = h >> 2, kv = h & 3;
    const int qcol0 = g * 512 + kv * 128;
    const int kcol0 = kv * 128;
    const int ocol0 = (kv * 4 + g) * 128;
    const __half* vp = Vt + (size_t)kv * 128 * N_TOK;

    extern __shared__ char smem[];
    const uint32_t sbase = smem_u32(smem);

    const int tid = threadIdx.x;
    const int lane = tid & 31;
    const int warp_m = tid >> 5;
    const int q4 = lane >> 2, l4 = lane & 3;
    const int qq = lane >> 3;
    const int rowA = (lane & 7) + (qq & 1) * 8;
    const int colA = (qq >> 1) * 16;
    const int rowB = (lane & 7) + (qq >> 1) * 8;
    const int colB = (qq & 1) * 16;
    const float SCALE = 0.08838834764831845f;

#pragma unroll
    for (int i = 0; i < 8; ++i) {
        int idx = tid + i * 256;
        int r = idx >> 4, c = idx & 15;
        size_t go = (size_t)(qt * 128 + r) * D_MODEL + qcol0 + c * 8;
        *(uint4*)(smem + OQ + r * RSQ + c * 16) = *(const uint4*)(Qs + go);
    }

    // issue K(0)
    {
#pragma unroll
        for (int i = 0; i < 4; ++i) {
            int idx = tid + i * 256;
            int r = idx >> 4, c = idx & 15;
            cpa16(sbase + OKST + r * RSQ + c * 16,
                  Ks + (size_t)r * KV_D + kcol0 + c * 8);
        }
        CPA_COMMIT;
    }

    float o[16][4];
#pragma unroll
    for (int f = 0; f < 16; ++f)
#pragma unroll
        for (int e = 0; e < 4; ++e) o[f][e] = 0.f;
    float m0 = -1e30f, m1 = -1e30f, l0 = 0.f, l1 = 0.f;

    const int nkt = 2 * qt + 2;
    for (int kt = 0; kt < nkt; ++kt) {
        __syncthreads();

        // issue V(kt) and K(kt+1)
#pragma unroll
        for (int i = 0; i < 4; ++i) {
            int idx = tid + i * 256;
            int r = idx >> 3, c = idx & 7;
            cpa16(sbase + OV + r * RSV + c * 16,
                  vp + (size_t)r * N_TOK + kt * 64 + c * 8);
        }
        if (kt + 1 < nkt) {
            uint32_t kst = sbase + OKST + ((kt + 1) & 1) * 17408;
#pragma unroll
            for (int i = 0; i < 4; ++i) {
                int idx = tid + i * 256;
                int r = idx >> 4, c = idx & 15;
                cpa16(kst + r * RSQ + c * 16,
                      Ks + (size_t)((kt + 1) * 64 + r) * KV_D + kcol0 + c * 8);
            }
        }
        CPA_COMMIT;

        CPA_WAIT(1);
        __syncthreads();

        const int rbase = qt * 128 + warp_m * 16;
        const bool active = (kt * 64) <= (rbase + 15);
        const uint32_t kst = sbase + OKST + (kt & 1) * 17408;

        if (active) {
            float sacc[8][4];
#pragma unroll
            for (int j = 0; j < 8; ++j)
#pragma unroll
                for (int e = 0; e < 4; ++e) sacc[j][e] = 0.f;
#pragma unroll
            for (int ks = 0; ks < 8; ++ks) {
                uint32_t a[4];
                uint32_t ra = sbase + OQ + (warp_m * 16 + rowA) * RSQ + ks * 32 + colA;
                LDSM4(a, ra);
#pragma unroll
                for (int p = 0; p < 2; ++p) {
                    uint32_t b[2][4];
#pragma unroll
                    for (int u = 0; u < 2; ++u) {
                        uint32_t rb = kst + ((p * 2 + u) * 16 + rowB) * RSQ + ks * 32 + colB;
                        LDSM4(b[u], rb);
                    }
#pragma unroll
                    for (int u = 0; u < 2; ++u)
#pragma unroll
                        for (int half = 0; half < 2; ++half)
                            MMAF16(sacc[(p * 2 + u) * 2 + half], a, b[u][half * 2], b[u][half * 2 + 1]);
                }
            }
            const bool needMask = (kt * 64 + 63) > rbase;
#pragma unroll
            for (int j = 0; j < 8; ++j)
#pragma unroll
                for (int e = 0; e < 4; ++e) {
                    float v = sacc[j][e] * SCALE;
                    if (needMask) {
                        int rg = rbase + q4 + (e >> 1) * 8;
                        int kg = kt * 64 + j * 8 + l4 * 2 + (e & 1);
                        if (kg > rg) v = -1e30f;
                    }
                    sacc[j][e] = v;
                }
            float mx0 = -1e30f, mx1 = -1e30f;
#pragma unroll
            for (int j = 0; j < 8; ++j) {
                mx0 = fmaxf(mx0, fmaxf(sacc[j][0], sacc[j][1]));
                mx1 = fmaxf(mx1, fmaxf(sacc[j][2], sacc[j][3]));
            }
            mx0 = fmaxf(mx0, __shfl_xor_sync(0xffffffffu, mx0, 1));
            mx0 = fmaxf(mx0, __shfl_xor_sync(0xffffffffu, mx0, 2));
            mx1 = fmaxf(mx1, __shfl_xor_sync(0xffffffffu, mx1, 1));
            mx1 = fmaxf(mx1, __shfl_xor_sync(0xffffffffu, mx1, 2));
            float nm0 = fmaxf(m0, mx0), nm1 = fmaxf(m1, mx1);
            float corr0 = fexp(m0 - nm0), corr1 = fexp(m1 - nm1);
            m0 = nm0; m1 = nm1;
            float s0 = 0.f, s1 = 0.f;
            uint32_t prow0 = sbase + OP + (warp_m * 16 + q4) * RSV + l4 * 4;
            uint32_t prow1 = prow0 + 8 * RSV;
#pragma unroll
            for (int j = 0; j < 8; ++j) {
                float p00 = fexp(sacc[j][0] - m0);
                float p01 = fexp(sacc[j][1] - m0);
                float p10 = fexp(sacc[j][2] - m1);
                float p11 = fexp(sacc[j][3] - m1);
                s0 += p00 + p01; s1 += p10 + p11;
                __half2 hp0 = __halves2half2(__float2half(p00), __float2half(p01));
                __half2 hp1 = __halves2half2(__float2half(p10), __float2half(p11));
                asm volatile("st.shared.b32 [%0], %1;" :: "r"(prow0 + j * 16), "r"(*(uint32_t*)&hp0));
                asm volatile("st.shared.b32 [%0], %1;" :: "r"(prow1 + j * 16), "r"(*(uint32_t*)&hp1));
            }
            s0 += __shfl_xor_sync(0xffffffffu, s0, 1);
            s0 += __shfl_xor_sync(0xffffffffu, s0, 2);
            s1 += __shfl_xor_sync(0xffffffffu, s1, 1);
            s1 += __shfl_xor_sync(0xffffffffu, s1, 2);
            l0 = l0 * corr0 + s0;
            l1 = l1 * corr1 + s1;
#pragma unroll
            for (int f = 0; f < 16; ++f) {
                o[f][0] *= corr0; o[f][1] *= corr0;
                o[f][2] *= corr1; o[f][3] *= corr1;
            }
        }

        CPA_WAIT(0);
        __syncthreads();

        if (active) {
#pragma unroll
            for (int ks = 0; ks < 4; ++ks) {
                uint32_t pa[4];
                uint32_t raddr = sbase + OP + (warp_m * 16 + rowA) * RSV + ks * 32 + colA;
                LDSM4(pa, raddr);
#pragma unroll
                for (int p = 0; p < 4; ++p) {
                    uint32_t vb[2][4];
#pragma unroll
                    for (int u = 0; u < 2; ++u) {
                        uint32_t b0 = sbase + OV + ((p * 2 + u) * 16 + rowB) * RSV + ks * 32 + colB;
                        LDSM4(vb[u], b0);
                    }
#pragma unroll
                    for (int u = 0; u < 2; ++u)
#pragma unroll
                        for (int half = 0; half < 2; ++half)
                            MMAF16(o[(p * 2 + u) * 2 + half], pa, vb[u][half * 2], vb[u][half * 2 + 1]);
                }
            }
        }
    }

    float i0 = 1.f / l0, i1 = 1.f / l1;
    int row0 = qt * 128 + warp_m * 16 + q4;
#pragma unroll
    for (int f = 0; f < 16; ++f) {
        int col = ocol0 + f * 8 + l4 * 2;
        *(__half2*)(cs + (size_t)row0 * D_MODEL + col) =
            __halves2half2(__float2half(o[f][0] * i0), __float2half(o[f][1] * i0));
        *(__half2*)(cs + (size_t)(row0 + 8) * D_MODEL + col) =
            __halves2half2(__float2half(o[f][2] * i1), __float2half(o[f][3] * i1));
    }
}

// ---------------------------------------------------------------------------
extern "C" void kernel_launch(void* const* d_in, const int* in_sizes, int n_in,
                              void* d_out, int out_size) {
    const float* x  = (const float*)d_in[0];
    const float* Wq = (const float*)d_in[1];
    const float* Wk = (const float*)d_in[2];
    const float* Wv = (const float*)d_in[3];
    const float* Wo = (const float*)d_in[4];
    float* out = (float*)d_out;

    __half *xs, *cs, *qs, *ks, *vt, *wq, *wk, *wv, *wo;
    float2* tab;
    cudaGetSymbolAddress((void**)&xs, g_xs);
    cudaGetSymbolAddress((void**)&cs, g_cs);
    cudaGetSymbolAddress((void**)&qs, g_Qs);
    cudaGetSymbolAddress((void**)&ks, g_Ks);
    cudaGetSymbolAddress((void**)&vt, g_Vt);
    cudaGetSymbolAddress((void**)&wq, g_WqT);
    cudaGetSymbolAddress((void**)&wk, g_WkT);
    cudaGetSymbolAddress((void**)&wv, g_WvT);
    cudaGetSymbolAddress((void**)&wo, g_WoT);
    cudaGetSymbolAddress((void**)&tab, g_rope);

    cudaFuncSetAttribute(hgemm_qkv, cudaFuncAttributeMaxDynamicSharedMemorySize, QKV_SMEM);
    cudaFuncSetAttribute(hgemm_o,   cudaFuncAttributeMaxDynamicSharedMemorySize, GSMEM);
    cudaFuncSetAttribute(flash_mma, cudaFuncAttributeMaxDynamicSharedMemorySize, FSMEM);

    prep_all<<<14848, 256>>>(x, Wq, Wk, Wv, Wo, xs, wq, wk, wv, wo, tab);
    hgemm_qkv<<<384, 256, QKV_SMEM>>>(xs, wq, wk, wv, qs, ks, vt, tab);
    flash_mma<<<dim3(N_TOK / 128, 16), 256, FSMEM>>>(qs, ks, vt, cs);
    hgemm_o<<<dim3(16, 16), 256, GSMEM>>>(cs, wo, out);

    (void)in_sizes; (void)n_in; (void)out_size;
}

// round 16
// speedup vs baseline: 2.3466x; 1.0842x over previous
#include <cuda_runtime.h>
#include <cuda_fp16.h>
#include <math.h>
#include <stdint.h>

#define N_TOK   2048
#define D_MODEL 2048
#define KV_D    512

// ---------------- scratch ---------------------------------------------------
__device__ __half g_xs[N_TOK * D_MODEL];
__device__ __half g_cs[N_TOK * D_MODEL];
__device__ __half g_Qs[N_TOK * D_MODEL];
__device__ __half g_Ks[N_TOK * KV_D];
__device__ __half g_Vt[KV_D * N_TOK];             // [kv][d][n]
__device__ __half g_WqT[D_MODEL * D_MODEL];
__device__ __half g_WkT[KV_D * D_MODEL];
__device__ __half g_WvT[KV_D * D_MODEL];
__device__ __half g_WoT[D_MODEL * D_MODEL];
__device__ float2 g_rope[N_TOK * 64];

__device__ __forceinline__ uint32_t smem_u32(const void* p) {
    uint32_t a;
    asm("{ .reg .u64 t; cvta.to.shared.u64 t, %1; cvt.u32.u64 %0, t; }"
        : "=r"(a) : "l"(p));
    return a;
}

#define LDSM4(r, addr)                                                        \
    asm volatile("ldmatrix.sync.aligned.m8n8.x4.shared.b16 {%0,%1,%2,%3}, [%4];" \
                 : "=r"((r)[0]), "=r"((r)[1]), "=r"((r)[2]), "=r"((r)[3])     \
                 : "r"(addr))

#define MMAF16(d, a, b0, b1)                                                  \
    asm volatile("mma.sync.aligned.m16n8k16.row.col.f32.f16.f16.f32 "         \
                 "{%0,%1,%2,%3}, {%4,%5,%6,%7}, {%8,%9}, {%0,%1,%2,%3};"      \
                 : "+f"((d)[0]), "+f"((d)[1]), "+f"((d)[2]), "+f"((d)[3])     \
                 : "r"((a)[0]), "r"((a)[1]), "r"((a)[2]), "r"((a)[3]),        \
                   "r"(b0), "r"(b1))

__device__ __forceinline__ void cpa16(uint32_t dst, const void* src) {
    asm volatile("cp.async.cg.shared.global [%0], [%1], 16;" :: "r"(dst), "l"(src));
}
#define CPA_COMMIT asm volatile("cp.async.commit_group;" ::: "memory")
#define CPA_WAIT(n) asm volatile("cp.async.wait_group %0;" :: "n"(n) : "memory")

__device__ __forceinline__ float fexp(float x) {
    float t = x * 1.4426950408889634f;
    t = fmaxf(t, -126.0f);
    float n = floorf(t);
    float f = t - n;
    float p = 1.5403530393283621e-4f;
    p = fmaf(p, f, 1.3333558146428443e-3f);
    p = fmaf(p, f, 9.6181291076284772e-3f);
    p = fmaf(p, f, 5.5504108664821580e-2f);
    p = fmaf(p, f, 2.4022650695910071e-1f);
    p = fmaf(p, f, 6.9314718055994531e-1f);
    p = fmaf(p, f, 1.0f);
    return __int_as_float(((int)n + 127) << 23) * p;
}

// ---------------------------------------------------------------------------
// Prep: x -> fp16 | all weights -> transposed fp16 single | rope table
// ---------------------------------------------------------------------------
__global__ void __launch_bounds__(256) prep_all(
    const float* __restrict__ x, const float* __restrict__ Wq,
    const float* __restrict__ Wk, const float* __restrict__ Wv,
    const float* __restrict__ Wo,
    __half* __restrict__ xs,
    __half* __restrict__ qt, __half* __restrict__ kt,
    __half* __restrict__ vt, __half* __restrict__ ot,
    float2* __restrict__ tab) {
    const int bid = blockIdx.x;
    const int tid = threadIdx.x;
    if (bid < 4096) {
        int i = (bid * 256 + tid) * 4;
        float4 v = *(const float4*)(x + i);
        __half2* p = (__half2*)(xs + i);
        p[0] = __halves2half2(__float2half(v.x), __float2half(v.y));
        p[1] = __halves2half2(__float2half(v.z), __float2half(v.w));
    } else if (bid < 14336) {
        __shared__ float t[32][33];
        int wb = bid - 4096;
        const float* in; __half* doh; int Ndim, nx, sid;
        if (wb < 4096)      { in = Wq; doh = qt; Ndim = D_MODEL; nx = 64; sid = wb; }
        else if (wb < 5120) { in = Wk; doh = kt; Ndim = KV_D;   nx = 16; sid = wb - 4096; }
        else if (wb < 6144) { in = Wv; doh = vt; Ndim = KV_D;   nx = 16; sid = wb - 5120; }
        else                { in = Wo; doh = ot; Ndim = D_MODEL; nx = 64; sid = wb - 6144; }
        int n0 = (sid % nx) * 32, k0 = (sid / nx) * 32;
        int tx = tid & 31, ty = tid >> 5;
#pragma unroll
        for (int i = 0; i < 4; ++i)
            t[ty + 8 * i][tx] = in[(size_t)(k0 + ty + 8 * i) * Ndim + n0 + tx];
        __syncthreads();
#pragma unroll
        for (int i = 0; i < 4; ++i) {
            int nl = ty + 8 * i;
            doh[(size_t)(n0 + nl) * D_MODEL + k0 + tx] = __float2half(t[tx][nl]);
        }
    } else {
        int idx = (bid - 14336) * 256 + tid;
        int t = idx >> 6, i = idx & 63;
        double inv = exp(-9.210340371976184 * ((double)i / 64.0));
        double ang = (double)t * inv;
        double k = floor(ang * 0.15915494309189535);
        float r = (float)(ang - k * 6.283185307179586);
        float s, c;
        sincosf(r, &s, &c);
        tab[idx] = make_float2(c, s);
    }
}

// ---------------------------------------------------------------------------
// cp.async 3-stage single-pass fp16 GEMM core. BM=BN=128, BK=32, 256 threads.
// ---------------------------------------------------------------------------
#define GRS    80
#define GTB    (128 * GRS)
#define GSTRIDE (2 * GTB)
#define GSMEM  (3 * GSTRIDE)     // 61440 (mainloop)
#define QKV_SMEM 69632           // max(mainloop 61440, V-transpose epi 67584)

__device__ __forceinline__ void gemm_issue(
    uint32_t sbase, int slot, int c, int K, int tid,
    const __half* pA, const __half* pB) {
    uint32_t stage = sbase + slot * GSTRIDE;
    const __half* bases[2] = {pA, pB};
#pragma unroll
    for (int t = 0; t < 2; ++t) {
#pragma unroll
        for (int i = 0; i < 2; ++i) {
            int idx = tid + i * 256;
            int r = idx >> 2, cc = idx & 3;
            cpa16(stage + t * GTB + r * GRS + cc * 16,
                  (const char*)bases[t] + ((size_t)r * K + c * 32) * 2 + cc * 16);
        }
    }
}

__device__ __forceinline__ void gemm_core(
    const __half* __restrict__ pA, const __half* __restrict__ pB,
    int K, uint32_t sbase, float acc[2][8][4]) {
    const int tid = threadIdx.x;
    const int lane = tid & 31;
    const int wid = tid >> 5;
    const int warp_m = wid & 3;
    const int warp_n = wid >> 2;
    const int q = lane >> 3;
    const int rowA = (lane & 7) + (q & 1) * 8;
    const int colA = (q >> 1) * 16;
    const int rowB = (lane & 7) + (q >> 1) * 8;
    const int colB = (q & 1) * 16;

    const int NC = K / 32;
    gemm_issue(sbase, 0, 0, K, tid, pA, pB);
    CPA_COMMIT;
    gemm_issue(sbase, 1, 1, K, tid, pA, pB);
    CPA_COMMIT;

    int slot = 0;
    for (int c = 0; c < NC; ++c) {
        CPA_WAIT(1);
        __syncthreads();
        if (c + 2 < NC) {
            int ns = slot + 2;
            if (ns >= 3) ns -= 3;
            gemm_issue(sbase, ns, c + 2, K, tid, pA, pB);
        }
        CPA_COMMIT;

        const uint32_t sb = sbase + slot * GSTRIDE;
#pragma unroll
        for (int ks = 0; ks < 2; ++ks) {
            uint32_t a[2][4], b[4][4];
#pragma unroll
            for (int im = 0; im < 2; ++im) {
                uint32_t ra = sb + (warp_m * 32 + im * 16 + rowA) * GRS + ks * 32 + colA;
                LDSM4(a[im], ra);
            }
#pragma unroll
            for (int ib = 0; ib < 4; ++ib) {
                uint32_t rb = sb + GTB + (warp_n * 64 + ib * 16 + rowB) * GRS + ks * 32 + colB;
                LDSM4(b[ib], rb);
            }
#pragma unroll
            for (int im = 0; im < 2; ++im)
#pragma unroll
                for (int j = 0; j < 8; ++j) {
                    const int f = j >> 1, h = (j & 1) * 2;
                    MMAF16(acc[im][j], a[im], b[f][h], b[f][h + 1]);
                }
        }
        if (++slot == 3) slot = 0;
    }
}

// ---- fused Q+K+V projection (384 uniform 1-pass blocks) -------------------
__global__ void __launch_bounds__(256) hgemm_qkv(
    const __half* __restrict__ A,
    const __half* __restrict__ QB, const __half* __restrict__ KB,
    const __half* __restrict__ VB,
    __half* __restrict__ qs, __half* __restrict__ ks, __half* __restrict__ vt,
    const float2* __restrict__ tab) {
    extern __shared__ char smem[];
    const uint32_t sbase = smem_u32(smem);
    const int bid = blockIdx.x;
    const int K = D_MODEL;
    int kind, m0, n0;
    const __half* B;
    if (bid < 64)       { kind = 1; m0 = (bid >> 2) * 128; n0 = (bid & 3) * 128; B = KB; }
    else if (bid < 128) { int s = bid - 64; kind = 2; m0 = (s >> 2) * 128; n0 = (s & 3) * 128; B = VB; }
    else                { int s = bid - 128; kind = 0; m0 = (s >> 4) * 128; n0 = (s & 15) * 128; B = QB; }

    float acc[2][8][4];
#pragma unroll
    for (int im = 0; im < 2; ++im)
#pragma unroll
        for (int j = 0; j < 8; ++j)
#pragma unroll
            for (int e = 0; e < 4; ++e) acc[im][j][e] = 0.f;
    gemm_core(A + (size_t)m0 * K, B + (size_t)n0 * K, K, sbase, acc);

    const int tid = threadIdx.x;
    const int lane = tid & 31, wid = tid >> 5;
    const int q4 = lane >> 2, l4 = lane & 3;
    if (kind != 2) {
        const int N = (kind == 0) ? D_MODEL : KV_D;
        __half* dst = (kind == 0) ? qs : ks;
#pragma unroll
        for (int im = 0; im < 2; ++im)
#pragma unroll
            for (int j = 0; j < 8; ++j) {
                int row = m0 + (wid & 3) * 32 + im * 16 + q4;
                int col = n0 + (wid >> 2) * 64 + j * 8 + l4 * 2;
#pragma unroll
                for (int rr = 0; rr < 2; ++rr) {
                    int r = row + rr * 8;
                    float v0 = acc[im][j][rr * 2], v1 = acc[im][j][rr * 2 + 1];
                    float2 cs = tab[r * 64 + ((col & 127) >> 1)];
                    float oe = v0 * cs.x - v1 * cs.y;
                    float oo = v0 * cs.y + v1 * cs.x;
                    *(__half2*)(dst + (size_t)r * N + col) =
                        __halves2half2(__float2half(oe), __float2half(oo));
                }
            }
    } else {
        // V: transpose via smem (128*132*4 = 67584 B <= QKV_SMEM)
        __syncthreads();
        float* tS = (float*)smem;  // [128][132]
#pragma unroll
        for (int im = 0; im < 2; ++im)
#pragma unroll
            for (int j = 0; j < 8; ++j) {
                int r = (wid & 3) * 32 + im * 16 + q4;
                int cl = (wid >> 2) * 64 + j * 8 + l4 * 2;
                tS[cl * 132 + r] = acc[im][j][0];
                tS[(cl + 1) * 132 + r] = acc[im][j][1];
                tS[cl * 132 + r + 8] = acc[im][j][2];
                tS[(cl + 1) * 132 + r + 8] = acc[im][j][3];
            }
        __syncthreads();
        const int dkv = n0 >> 7;
        const int d = tid >> 1, half = (tid & 1) * 64;
        size_t dst = (size_t)dkv * 128 * N_TOK + (size_t)d * N_TOK + m0 + half;
#pragma unroll
        for (int k = 0; k < 64; k += 2) {
            *(__half2*)(vt + dst + k) =
                __halves2half2(__float2half(tS[d * 132 + half + k]),
                               __float2half(tS[d * 132 + half + k + 1]));
        }
    }
}

// ---- output projection ----------------------------------------------------
__global__ void __launch_bounds__(256) hgemm_o(
    const __half* __restrict__ A, const __half* __restrict__ B,
    float* __restrict__ C) {
    extern __shared__ char smem[];
    const uint32_t sbase = smem_u32(smem);
    const int m0 = blockIdx.y * 128, n0 = blockIdx.x * 128;
    const int K = D_MODEL, N = D_MODEL;
    float acc[2][8][4];
#pragma unroll
    for (int im = 0; im < 2; ++im)
#pragma unroll
        for (int j = 0; j < 8; ++j)
#pragma unroll
            for (int e = 0; e < 4; ++e) acc[im][j][e] = 0.f;
    gemm_core(A + (size_t)m0 * K, B + (size_t)n0 * K, K, sbase, acc);
    const int lane = threadIdx.x & 31, wid = threadIdx.x >> 5;
#pragma unroll
    for (int im = 0; im < 2; ++im)
#pragma unroll
        for (int j = 0; j < 8; ++j) {
            int row = m0 + (wid & 3) * 32 + im * 16 + (lane >> 2);
            int col = n0 + (wid >> 2) * 64 + j * 8 + (lane & 3) * 2;
            *(float2*)(C + (size_t)row * N + col) = make_float2(acc[im][j][0], acc[im][j][1]);
            *(float2*)(C + (size_t)(row + 8) * N + col) = make_float2(acc[im][j][2], acc[im][j][3]);
        }
}

// ---------------------------------------------------------------------------
// Flash attention: BM=64 q-rows, 4 warps (128 threads), grid (32, 16).
// Every warp active every iteration (loop kt=0..qt). 2 CTAs/SM.
// ---------------------------------------------------------------------------
#define RSQ 272
#define RSV 144
#define FOQ    0                 // Q: 64*272 = 17408
#define FOKST  17408             // K stages: 2 * 17408
#define FOV    52224             // V: 128*144 = 18432
#define FOP    70656             // P: 64*144 = 9216
#define FSMEM  79872

__global__ void __launch_bounds__(128, 2) flash_mma(
    const __half* __restrict__ Qs, const __half* __restrict__ Ks,
    const __half* __restrict__ Vt, __half* __restrict__ cs) {
    const int qt = gridDim.x - 1 - blockIdx.x;   // long blocks first
    const int h  = blockIdx.y;
    const int g  = h >> 2, kv = h & 3;
    const int qcol0 = g * 512 + kv * 128;
    const int kcol0 = kv * 128;
    const int ocol0 = (kv * 4 + g) * 128;
    const __half* vp = Vt + (size_t)kv * 128 * N_TOK;

    extern __shared__ char smem[];
    const uint32_t sbase = smem_u32(smem);

    const int tid = threadIdx.x;
    const int lane = tid & 31;
    const int warp_m = tid >> 5;                 // 0..3
    const int q4 = lane >> 2, l4 = lane & 3;
    const int qq = lane >> 3;
    const int rowA = (lane & 7) + (qq & 1) * 8;
    const int colA = (qq >> 1) * 16;
    const int rowB = (lane & 7) + (qq >> 1) * 8;
    const int colB = (qq & 1) * 16;
    const float SCALE = 0.08838834764831845f;

    // Q tile (64 rows) -> smem
#pragma unroll
    for (int i = 0; i < 8; ++i) {
        int idx = tid + i * 128;
        int r = idx >> 4, c = idx & 15;
        size_t go = (size_t)(qt * 64 + r) * D_MODEL + qcol0 + c * 8;
        *(uint4*)(smem + FOQ + r * RSQ + c * 16) = *(const uint4*)(Qs + go);
    }

    // issue K(0)
    {
#pragma unroll
        for (int i = 0; i < 8; ++i) {
            int idx = tid + i * 128;
            int r = idx >> 4, c = idx & 15;
            cpa16(sbase + FOKST + r * RSQ + c * 16,
                  Ks + (size_t)r * KV_D + kcol0 + c * 8);
        }
        CPA_COMMIT;
    }

    float o[16][4];
#pragma unroll
    for (int f = 0; f < 16; ++f)
#pragma unroll
        for (int e = 0; e < 4; ++e) o[f][e] = 0.f;
    float m0 = -1e30f, m1 = -1e30f, l0 = 0.f, l1 = 0.f;

    const int nkt = qt + 1;
    for (int kt = 0; kt < nkt; ++kt) {
        __syncthreads();

        // issue V(kt) and K(kt+1)
#pragma unroll
        for (int i = 0; i < 8; ++i) {
            int idx = tid + i * 128;
            int r = idx >> 3, c = idx & 7;
            cpa16(sbase + FOV + r * RSV + c * 16,
                  vp + (size_t)r * N_TOK + kt * 64 + c * 8);
        }
        if (kt + 1 < nkt) {
            uint32_t kst = sbase + FOKST + ((kt + 1) & 1) * 17408;
#pragma unroll
            for (int i = 0; i < 8; ++i) {
                int idx = tid + i * 128;
                int r = idx >> 4, c = idx & 15;
                cpa16(kst + r * RSQ + c * 16,
                      Ks + (size_t)((kt + 1) * 64 + r) * KV_D + kcol0 + c * 8);
            }
        }
        CPA_COMMIT;

        CPA_WAIT(1);
        __syncthreads();

        const int rbase = qt * 64 + warp_m * 16;
        const uint32_t kst = sbase + FOKST + (kt & 1) * 17408;

        // S = Q K^T (16 x 64 per warp)
        float sacc[8][4];
#pragma unroll
        for (int j = 0; j < 8; ++j)
#pragma unroll
            for (int e = 0; e < 4; ++e) sacc[j][e] = 0.f;
#pragma unroll
        for (int ks = 0; ks < 8; ++ks) {
            uint32_t a[4];
            uint32_t ra = sbase + FOQ + (warp_m * 16 + rowA) * RSQ + ks * 32 + colA;
            LDSM4(a, ra);
#pragma unroll
            for (int p = 0; p < 2; ++p) {
                uint32_t b[2][4];
#pragma unroll
                for (int u = 0; u < 2; ++u) {
                    uint32_t rb = kst + ((p * 2 + u) * 16 + rowB) * RSQ + ks * 32 + colB;
                    LDSM4(b[u], rb);
                }
#pragma unroll
                for (int u = 0; u < 2; ++u)
#pragma unroll
                    for (int half = 0; half < 2; ++half)
                        MMAF16(sacc[(p * 2 + u) * 2 + half], a, b[u][half * 2], b[u][half * 2 + 1]);
            }
        }
        const bool needMask = (kt == qt);   // only diagonal tile masks
#pragma unroll
        for (int j = 0; j < 8; ++j)
#pragma unroll
            for (int e = 0; e < 4; ++e) {
                float v = sacc[j][e] * SCALE;
                if (needMask) {
                    int rg = rbase + q4 + (e >> 1) * 8;
                    int kg = kt * 64 + j * 8 + l4 * 2 + (e & 1);
                    if (kg > rg) v = -1e30f;
                }
                sacc[j][e] = v;
            }
        float mx0 = -1e30f, mx1 = -1e30f;
#pragma unroll
        for (int j = 0; j < 8; ++j) {
            mx0 = fmaxf(mx0, fmaxf(sacc[j][0], sacc[j][1]));
            mx1 = fmaxf(mx1, fmaxf(sacc[j][2], sacc[j][3]));
        }
        mx0 = fmaxf(mx0, __shfl_xor_sync(0xffffffffu, mx0, 1));
        mx0 = fmaxf(mx0, __shfl_xor_sync(0xffffffffu, mx0, 2));
        mx1 = fmaxf(mx1, __shfl_xor_sync(0xffffffffu, mx1, 1));
        mx1 = fmaxf(mx1, __shfl_xor_sync(0xffffffffu, mx1, 2));
        float nm0 = fmaxf(m0, mx0), nm1 = fmaxf(m1, mx1);
        float corr0 = fexp(m0 - nm0), corr1 = fexp(m1 - nm1);
        m0 = nm0; m1 = nm1;
        float s0 = 0.f, s1 = 0.f;
        uint32_t prow0 = sbase + FOP + (warp_m * 16 + q4) * RSV + l4 * 4;
        uint32_t prow1 = prow0 + 8 * RSV;
#pragma unroll
        for (int j = 0; j < 8; ++j) {
            float p00 = fexp(sacc[j][0] - m0);
            float p01 = fexp(sacc[j][1] - m0);
            float p10 = fexp(sacc[j][2] - m1);
            float p11 = fexp(sacc[j][3] - m1);
            s0 += p00 + p01; s1 += p10 + p11;
            __half2 hp0 = __halves2half2(__float2half(p00), __float2half(p01));
            __half2 hp1 = __halves2half2(__float2half(p10), __float2half(p11));
            asm volatile("st.shared.b32 [%0], %1;" :: "r"(prow0 + j * 16), "r"(*(uint32_t*)&hp0));
            asm volatile("st.shared.b32 [%0], %1;" :: "r"(prow1 + j * 16), "r"(*(uint32_t*)&hp1));
        }
        s0 += __shfl_xor_sync(0xffffffffu, s0, 1);
        s0 += __shfl_xor_sync(0xffffffffu, s0, 2);
        s1 += __shfl_xor_sync(0xffffffffu, s1, 1);
        s1 += __shfl_xor_sync(0xffffffffu, s1, 2);
        l0 = l0 * corr0 + s0;
        l1 = l1 * corr1 + s1;
#pragma unroll
        for (int f = 0; f < 16; ++f) {
            o[f][0] *= corr0; o[f][1] *= corr0;
            o[f][2] *= corr1; o[f][3] *= corr1;
        }

        CPA_WAIT(0);    // V(kt) complete
        __syncthreads();

        // O += P @ V
#pragma unroll
        for (int ks = 0; ks < 4; ++ks) {
            uint32_t pa[4];
            uint32_t raddr = sbase + FOP + (warp_m * 16 + rowA) * RSV + ks * 32 + colA;
            LDSM4(pa, raddr);
#pragma unroll
            for (int p = 0; p < 4; ++p) {
                uint32_t vb[2][4];
#pragma unroll
                for (int u = 0; u < 2; ++u) {
                    uint32_t b0 = sbase + FOV + ((p * 2 + u) * 16 + rowB) * RSV + ks * 32 + colB;
                    LDSM4(vb[u], b0);
                }
#pragma unroll
                for (int u = 0; u < 2; ++u)
#pragma unroll
                    for (int half = 0; half < 2; ++half)
                        MMAF16(o[(p * 2 + u) * 2 + half], pa, vb[u][half * 2], vb[u][half * 2 + 1]);
            }
        }
    }

    float i0 = 1.f / l0, i1 = 1.f / l1;
    int row0 = qt * 64 + warp_m * 16 + q4;
#pragma unroll
    for (int f = 0; f < 16; ++f) {
        int col = ocol0 + f * 8 + l4 * 2;
        *(__half2*)(cs + (size_t)row0 * D_MODEL + col) =
            __halves2half2(__float2half(o[f][0] * i0), __float2half(o[f][1] * i0));
        *(__half2*)(cs + (size_t)(row0 + 8) * D_MODEL + col) =
            __halves2half2(__float2half(o[f][2] * i1), __float2half(o[f][3] * i1));
    }
}

// ---------------------------------------------------------------------------
extern "C" void kernel_launch(void* const* d_in, const int* in_sizes, int n_in,
                              void* d_out, int out_size) {
    const float* x  = (const float*)d_in[0];
    const float* Wq = (const float*)d_in[1];
    const float* Wk = (const float*)d_in[2];
    const float* Wv = (const float*)d_in[3];
    const float* Wo = (const float*)d_in[4];
    float* out = (float*)d_out;

    __half *xs, *cs, *qs, *ks, *vt, *wq, *wk, *wv, *wo;
    float2* tab;
    cudaGetSymbolAddress((void**)&xs, g_xs);
    cudaGetSymbolAddress((void**)&cs, g_cs);
    cudaGetSymbolAddress((void**)&qs, g_Qs);
    cudaGetSymbolAddress((void**)&ks, g_Ks);
    cudaGetSymbolAddress((void**)&vt, g_Vt);
    cudaGetSymbolAddress((void**)&wq, g_WqT);
    cudaGetSymbolAddress((void**)&wk, g_WkT);
    cudaGetSymbolAddress((void**)&wv, g_WvT);
    cudaGetSymbolAddress((void**)&wo, g_WoT);
    cudaGetSymbolAddress((void**)&tab, g_rope);

    cudaFuncSetAttribute(hgemm_qkv, cudaFuncAttributeMaxDynamicSharedMemorySize, QKV_SMEM);
    cudaFuncSetAttribute(hgemm_o,   cudaFuncAttributeMaxDynamicSharedMemorySize, GSMEM);
    cudaFuncSetAttribute(flash_mma, cudaFuncAttributeMaxDynamicSharedMemorySize, FSMEM);

    prep_all<<<14848, 256>>>(x, Wq, Wk, Wv, Wo, xs, wq, wk, wv, wo, tab);
    hgemm_qkv<<<384, 256, QKV_SMEM>>>(xs, wq, wk, wv, qs, ks, vt, tab);
    flash_mma<<<dim3(N_TOK / 64, 16), 128, FSMEM>>>(qs, ks, vt, cs);
    hgemm_o<<<dim3(16, 16), 256, GSMEM>>>(cs, wo, out);

    (void)in_sizes; (void)n_in; (void)out_size;
}

// round 17
// speedup vs baseline: 2.3931x; 1.0198x over previous
#include <cuda_runtime.h>
#include <cuda_fp16.h>
#include <math.h>
#include <stdint.h>

#define N_TOK   2048
#define D_MODEL 2048
#define KV_D    512

// ---------------- scratch ---------------------------------------------------
__device__ __half g_xs[N_TOK * D_MODEL];
__device__ __half g_cs[N_TOK * D_MODEL];
__device__ __half g_Qs[N_TOK * D_MODEL];
__device__ __half g_Ks[N_TOK * KV_D];
__device__ __half g_Vt[KV_D * N_TOK];             // [kv][d][n]
__device__ __half g_WqT[D_MODEL * D_MODEL];
__device__ __half g_WkT[KV_D * D_MODEL];
__device__ __half g_WvT[KV_D * D_MODEL];
__device__ __half g_WoT[D_MODEL * D_MODEL];
__device__ float2 g_rope[N_TOK * 64];

__device__ __forceinline__ uint32_t smem_u32(const void* p) {
    uint32_t a;
    asm("{ .reg .u64 t; cvta.to.shared.u64 t, %1; cvt.u32.u64 %0, t; }"
        : "=r"(a) : "l"(p));
    return a;
}

#define LDSM4(r, addr)                                                        \
    asm volatile("ldmatrix.sync.aligned.m8n8.x4.shared.b16 {%0,%1,%2,%3}, [%4];" \
                 : "=r"((r)[0]), "=r"((r)[1]), "=r"((r)[2]), "=r"((r)[3])     \
                 : "r"(addr))

#define MMAF16(d, a, b0, b1)                                                  \
    asm volatile("mma.sync.aligned.m16n8k16.row.col.f32.f16.f16.f32 "         \
                 "{%0,%1,%2,%3}, {%4,%5,%6,%7}, {%8,%9}, {%0,%1,%2,%3};"      \
                 : "+f"((d)[0]), "+f"((d)[1]), "+f"((d)[2]), "+f"((d)[3])     \
                 : "r"((a)[0]), "r"((a)[1]), "r"((a)[2]), "r"((a)[3]),        \
                   "r"(b0), "r"(b1))

__device__ __forceinline__ void cpa16(uint32_t dst, const void* src) {
    asm volatile("cp.async.cg.shared.global [%0], [%1], 16;" :: "r"(dst), "l"(src));
}
#define CPA_COMMIT asm volatile("cp.async.commit_group;" ::: "memory")
#define CPA_WAIT(n) asm volatile("cp.async.wait_group %0;" :: "n"(n) : "memory")

__device__ __forceinline__ float fexp(float x) {
    float t = x * 1.4426950408889634f;
    t = fmaxf(t, -126.0f);
    float n = floorf(t);
    float f = t - n;
    float p = 1.5403530393283621e-4f;
    p = fmaf(p, f, 1.3333558146428443e-3f);
    p = fmaf(p, f, 9.6181291076284772e-3f);
    p = fmaf(p, f, 5.5504108664821580e-2f);
    p = fmaf(p, f, 2.4022650695910071e-1f);
    p = fmaf(p, f, 6.9314718055994531e-1f);
    p = fmaf(p, f, 1.0f);
    return __int_as_float(((int)n + 127) << 23) * p;
}

// ---------------------------------------------------------------------------
// Prep: x -> fp16 | all weights -> transposed fp16 single | rope table
// ---------------------------------------------------------------------------
__global__ void __launch_bounds__(256) prep_all(
    const float* __restrict__ x, const float* __restrict__ Wq,
    const float* __restrict__ Wk, const float* __restrict__ Wv,
    const float* __restrict__ Wo,
    __half* __restrict__ xs,
    __half* __restrict__ qt, __half* __restrict__ kt,
    __half* __restrict__ vt, __half* __restrict__ ot,
    float2* __restrict__ tab) {
    const int bid = blockIdx.x;
    const int tid = threadIdx.x;
    if (bid < 4096) {
        int i = (bid * 256 + tid) * 4;
        float4 v = *(const float4*)(x + i);
        __half2* p = (__half2*)(xs + i);
        p[0] = __halves2half2(__float2half(v.x), __float2half(v.y));
        p[1] = __halves2half2(__float2half(v.z), __float2half(v.w));
    } else if (bid < 14336) {
        __shared__ float t[32][33];
        int wb = bid - 4096;
        const float* in; __half* doh; int Ndim, nx, sid;
        if (wb < 4096)      { in = Wq; doh = qt; Ndim = D_MODEL; nx = 64; sid = wb; }
        else if (wb < 5120) { in = Wk; doh = kt; Ndim = KV_D;   nx = 16; sid = wb - 4096; }
        else if (wb < 6144) { in = Wv; doh = vt; Ndim = KV_D;   nx = 16; sid = wb - 5120; }
        else                { in = Wo; doh = ot; Ndim = D_MODEL; nx = 64; sid = wb - 6144; }
        int n0 = (sid % nx) * 32, k0 = (sid / nx) * 32;
        int tx = tid & 31, ty = tid >> 5;
#pragma unroll
        for (int i = 0; i < 4; ++i)
            t[ty + 8 * i][tx] = in[(size_t)(k0 + ty + 8 * i) * Ndim + n0 + tx];
        __syncthreads();
#pragma unroll
        for (int i = 0; i < 4; ++i) {
            int nl = ty + 8 * i;
            doh[(size_t)(n0 + nl) * D_MODEL + k0 + tx] = __float2half(t[tx][nl]);
        }
    } else {
        int idx = (bid - 14336) * 256 + tid;
        int t = idx >> 6, i = idx & 63;
        double inv = exp(-9.210340371976184 * ((double)i / 64.0));
        double ang = (double)t * inv;
        double k = floor(ang * 0.15915494309189535);
        float r = (float)(ang - k * 6.283185307179586);
        float s, c;
        sincosf(r, &s, &c);
        tab[idx] = make_float2(c, s);
    }
}

// ---------------------------------------------------------------------------
// cp.async 3-stage single-pass fp16 GEMM core. BM=BN=128, BK=32, 256 threads.
// ---------------------------------------------------------------------------
#define GRS    80
#define GTB    (128 * GRS)
#define GSTRIDE (2 * GTB)
#define GSMEM  (3 * GSTRIDE)     // 61440 (mainloop)
#define QKV_SMEM 69632           // max(mainloop 61440, V-transpose epi 67584)

__device__ __forceinline__ void gemm_issue(
    uint32_t sbase, int slot, int c, int K, int tid,
    const __half* pA, const __half* pB) {
    uint32_t stage = sbase + slot * GSTRIDE;
    const __half* bases[2] = {pA, pB};
#pragma unroll
    for (int t = 0; t < 2; ++t) {
#pragma unroll
        for (int i = 0; i < 2; ++i) {
            int idx = tid + i * 256;
            int r = idx >> 2, cc = idx & 3;
            cpa16(stage + t * GTB + r * GRS + cc * 16,
                  (const char*)bases[t] + ((size_t)r * K + c * 32) * 2 + cc * 16);
        }
    }
}

__device__ __forceinline__ void gemm_core(
    const __half* __restrict__ pA, const __half* __restrict__ pB,
    int K, uint32_t sbase, float acc[2][8][4]) {
    const int tid = threadIdx.x;
    const int lane = tid & 31;
    const int wid = tid >> 5;
    const int warp_m = wid & 3;
    const int warp_n = wid >> 2;
    const int q = lane >> 3;
    const int rowA = (lane & 7) + (q & 1) * 8;
    const int colA = (q >> 1) * 16;
    const int rowB = (lane & 7) + (q >> 1) * 8;
    const int colB = (q & 1) * 16;

    const int NC = K / 32;
    gemm_issue(sbase, 0, 0, K, tid, pA, pB);
    CPA_COMMIT;
    gemm_issue(sbase, 1, 1, K, tid, pA, pB);
    CPA_COMMIT;

    int slot = 0;
    for (int c = 0; c < NC; ++c) {
        CPA_WAIT(1);
        __syncthreads();
        if (c + 2 < NC) {
            int ns = slot + 2;
            if (ns >= 3) ns -= 3;
            gemm_issue(sbase, ns, c + 2, K, tid, pA, pB);
        }
        CPA_COMMIT;

        const uint32_t sb = sbase + slot * GSTRIDE;
#pragma unroll
        for (int ks = 0; ks < 2; ++ks) {
            uint32_t a[2][4], b[4][4];
#pragma unroll
            for (int im = 0; im < 2; ++im) {
                uint32_t ra = sb + (warp_m * 32 + im * 16 + rowA) * GRS + ks * 32 + colA;
                LDSM4(a[im], ra);
            }
#pragma unroll
            for (int ib = 0; ib < 4; ++ib) {
                uint32_t rb = sb + GTB + (warp_n * 64 + ib * 16 + rowB) * GRS + ks * 32 + colB;
                LDSM4(b[ib], rb);
            }
#pragma unroll
            for (int im = 0; im < 2; ++im)
#pragma unroll
                for (int j = 0; j < 8; ++j) {
                    const int f = j >> 1, h = (j & 1) * 2;
                    MMAF16(acc[im][j], a[im], b[f][h], b[f][h + 1]);
                }
        }
        if (++slot == 3) slot = 0;
    }
}

// ---- fused Q+K+V projection (384 uniform 1-pass blocks) -------------------
__global__ void __launch_bounds__(256) hgemm_qkv(
    const __half* __restrict__ A,
    const __half* __restrict__ QB, const __half* __restrict__ KB,
    const __half* __restrict__ VB,
    __half* __restrict__ qs, __half* __restrict__ ks, __half* __restrict__ vt,
    const float2* __restrict__ tab) {
    extern __shared__ char smem[];
    const uint32_t sbase = smem_u32(smem);
    const int bid = blockIdx.x;
    const int K = D_MODEL;
    int kind, m0, n0;
    const __half* B;
    if (bid < 64)       { kind = 1; m0 = (bid >> 2) * 128; n0 = (bid & 3) * 128; B = KB; }
    else if (bid < 128) { int s = bid - 64; kind = 2; m0 = (s >> 2) * 128; n0 = (s & 3) * 128; B = VB; }
    else                { int s = bid - 128; kind = 0; m0 = (s >> 4) * 128; n0 = (s & 15) * 128; B = QB; }

    float acc[2][8][4];
#pragma unroll
    for (int im = 0; im < 2; ++im)
#pragma unroll
        for (int j = 0; j < 8; ++j)
#pragma unroll
            for (int e = 0; e < 4; ++e) acc[im][j][e] = 0.f;
    gemm_core(A + (size_t)m0 * K, B + (size_t)n0 * K, K, sbase, acc);

    const int tid = threadIdx.x;
    const int lane = tid & 31, wid = tid >> 5;
    const int q4 = lane >> 2, l4 = lane & 3;
    if (kind != 2) {
        const int N = (kind == 0) ? D_MODEL : KV_D;
        __half* dst = (kind == 0) ? qs : ks;
#pragma unroll
        for (int im = 0; im < 2; ++im)
#pragma unroll
            for (int j = 0; j < 8; ++j) {
                int row = m0 + (wid & 3) * 32 + im * 16 + q4;
                int col = n0 + (wid >> 2) * 64 + j * 8 + l4 * 2;
#pragma unroll
                for (int rr = 0; rr < 2; ++rr) {
                    int r = row + rr * 8;
                    float v0 = acc[im][j][rr * 2], v1 = acc[im][j][rr * 2 + 1];
                    float2 cs = tab[r * 64 + ((col & 127) >> 1)];
                    float oe = v0 * cs.x - v1 * cs.y;
                    float oo = v0 * cs.y + v1 * cs.x;
                    *(__half2*)(dst + (size_t)r * N + col) =
                        __halves2half2(__float2half(oe), __float2half(oo));
                }
            }
    } else {
        // V: transpose via smem (128*132*4 = 67584 B <= QKV_SMEM)
        __syncthreads();
        float* tS = (float*)smem;  // [128][132]
#pragma unroll
        for (int im = 0; im < 2; ++im)
#pragma unroll
            for (int j = 0; j < 8; ++j) {
                int r = (wid & 3) * 32 + im * 16 + q4;
                int cl = (wid >> 2) * 64 + j * 8 + l4 * 2;
                tS[cl * 132 + r] = acc[im][j][0];
                tS[(cl + 1) * 132 + r] = acc[im][j][1];
                tS[cl * 132 + r + 8] = acc[im][j][2];
                tS[(cl + 1) * 132 + r + 8] = acc[im][j][3];
            }
        __syncthreads();
        const int dkv = n0 >> 7;
        const int d = tid >> 1, half = (tid & 1) * 64;
        size_t dst = (size_t)dkv * 128 * N_TOK + (size_t)d * N_TOK + m0 + half;
#pragma unroll
        for (int k = 0; k < 64; k += 2) {
            *(__half2*)(vt + dst + k) =
                __halves2half2(__float2half(tS[d * 132 + half + k]),
                               __float2half(tS[d * 132 + half + k + 1]));
        }
    }
}

// ---- output projection ----------------------------------------------------
__global__ void __launch_bounds__(256) hgemm_o(
    const __half* __restrict__ A, const __half* __restrict__ B,
    float* __restrict__ C) {
    extern __shared__ char smem[];
    const uint32_t sbase = smem_u32(smem);
    const int m0 = blockIdx.y * 128, n0 = blockIdx.x * 128;
    const int K = D_MODEL, N = D_MODEL;
    float acc[2][8][4];
#pragma unroll
    for (int im = 0; im < 2; ++im)
#pragma unroll
        for (int j = 0; j < 8; ++j)
#pragma unroll
            for (int e = 0; e < 4; ++e) acc[im][j][e] = 0.f;
    gemm_core(A + (size_t)m0 * K, B + (size_t)n0 * K, K, sbase, acc);
    const int lane = threadIdx.x & 31, wid = threadIdx.x >> 5;
#pragma unroll
    for (int im = 0; im < 2; ++im)
#pragma unroll
        for (int j = 0; j < 8; ++j) {
            int row = m0 + (wid & 3) * 32 + im * 16 + (lane >> 2);
            int col = n0 + (wid >> 2) * 64 + j * 8 + (lane & 3) * 2;
            *(float2*)(C + (size_t)row * N + col) = make_float2(acc[im][j][0], acc[im][j][1]);
            *(float2*)(C + (size_t)(row + 8) * N + col) = make_float2(acc[im][j][2], acc[im][j][3]);
        }
}

// ---------------------------------------------------------------------------
// Flash attention: BM=64, 4 warps, grid (32, 16). P kept in registers
// (C-fragment == A-fragment repack), no P smem. 3 CTAs/SM.
// ---------------------------------------------------------------------------
#define RSQ 272
#define RSV 144
#define FOQ    0                 // Q: 64*272 = 17408
#define FOKST  17408             // K stages: 2 * 17408
#define FOV    52224             // V: 128*144 = 18432
#define FSMEM  70656

__global__ void __launch_bounds__(128, 3) flash_mma(
    const __half* __restrict__ Qs, const __half* __restrict__ Ks,
    const __half* __restrict__ Vt, __half* __restrict__ cs) {
    const int qt = gridDim.x - 1 - blockIdx.x;   // long blocks first
    const int h  = blockIdx.y;
    const int g  = h >> 2, kv = h & 3;
    const int qcol0 = g * 512 + kv * 128;
    const int kcol0 = kv * 128;
    const int ocol0 = (kv * 4 + g) * 128;
    const __half* vp = Vt + (size_t)kv * 128 * N_TOK;

    extern __shared__ char smem[];
    const uint32_t sbase = smem_u32(smem);

    const int tid = threadIdx.x;
    const int lane = tid & 31;
    const int warp_m = tid >> 5;                 // 0..3
    const int q4 = lane >> 2, l4 = lane & 3;
    const int qq = lane >> 3;
    const int rowA = (lane & 7) + (qq & 1) * 8;
    const int colA = (qq >> 1) * 16;
    const int rowB = (lane & 7) + (qq >> 1) * 8;
    const int colB = (qq & 1) * 16;
    const float SCALE = 0.08838834764831845f;

    // Q tile (64 rows) -> smem
#pragma unroll
    for (int i = 0; i < 8; ++i) {
        int idx = tid + i * 128;
        int r = idx >> 4, c = idx & 15;
        size_t go = (size_t)(qt * 64 + r) * D_MODEL + qcol0 + c * 8;
        *(uint4*)(smem + FOQ + r * RSQ + c * 16) = *(const uint4*)(Qs + go);
    }

    // issue K(0)
    {
#pragma unroll
        for (int i = 0; i < 8; ++i) {
            int idx = tid + i * 128;
            int r = idx >> 4, c = idx & 15;
            cpa16(sbase + FOKST + r * RSQ + c * 16,
                  Ks + (size_t)r * KV_D + kcol0 + c * 8);
        }
        CPA_COMMIT;
    }

    float o[16][4];
#pragma unroll
    for (int f = 0; f < 16; ++f)
#pragma unroll
        for (int e = 0; e < 4; ++e) o[f][e] = 0.f;
    float m0 = -1e30f, m1 = -1e30f, l0 = 0.f, l1 = 0.f;

    const int nkt = qt + 1;
    for (int kt = 0; kt < nkt; ++kt) {
        __syncthreads();   // V(kt-1) reads + K buffer reads complete

        // issue V(kt) as its own group
#pragma unroll
        for (int i = 0; i < 8; ++i) {
            int idx = tid + i * 128;
            int r = idx >> 3, c = idx & 7;
            cpa16(sbase + FOV + r * RSV + c * 16,
                  vp + (size_t)r * N_TOK + kt * 64 + c * 8);
        }
        CPA_COMMIT;
        // issue K(kt+1) as its own group
        const bool hasNext = (kt + 1 < nkt);
        if (hasNext) {
            uint32_t kst = sbase + FOKST + ((kt + 1) & 1) * 17408;
#pragma unroll
            for (int i = 0; i < 8; ++i) {
                int idx = tid + i * 128;
                int r = idx >> 4, c = idx & 15;
                cpa16(kst + r * RSQ + c * 16,
                      Ks + (size_t)((kt + 1) * 64 + r) * KV_D + kcol0 + c * 8);
            }
            CPA_COMMIT;
            CPA_WAIT(2);   // K(kt) done; V(kt), K(kt+1) may pend
        } else {
            CPA_WAIT(1);   // K(kt) done; V(kt) may pend
        }
        __syncthreads();

        const int rbase = qt * 64 + warp_m * 16;
        const uint32_t kst = sbase + FOKST + (kt & 1) * 17408;

        // S = Q K^T (16 x 64 per warp)
        float sacc[8][4];
#pragma unroll
        for (int j = 0; j < 8; ++j)
#pragma unroll
            for (int e = 0; e < 4; ++e) sacc[j][e] = 0.f;
#pragma unroll
        for (int ks = 0; ks < 8; ++ks) {
            uint32_t a[4];
            uint32_t ra = sbase + FOQ + (warp_m * 16 + rowA) * RSQ + ks * 32 + colA;
            LDSM4(a, ra);
#pragma unroll
            for (int p = 0; p < 2; ++p) {
                uint32_t b[2][4];
#pragma unroll
                for (int u = 0; u < 2; ++u) {
                    uint32_t rb = kst + ((p * 2 + u) * 16 + rowB) * RSQ + ks * 32 + colB;
                    LDSM4(b[u], rb);
                }
#pragma unroll
                for (int u = 0; u < 2; ++u)
#pragma unroll
                    for (int half = 0; half < 2; ++half)
                        MMAF16(sacc[(p * 2 + u) * 2 + half], a, b[u][half * 2], b[u][half * 2 + 1]);
            }
        }
        const bool needMask = (kt == qt);
#pragma unroll
        for (int j = 0; j < 8; ++j)
#pragma unroll
            for (int e = 0; e < 4; ++e) {
                float v = sacc[j][e] * SCALE;
                if (needMask) {
                    int rg = rbase + q4 + (e >> 1) * 8;
                    int kg = kt * 64 + j * 8 + l4 * 2 + (e & 1);
                    if (kg > rg) v = -1e30f;
                }
                sacc[j][e] = v;
            }
        float mx0 = -1e30f, mx1 = -1e30f;
#pragma unroll
        for (int j = 0; j < 8; ++j) {
            mx0 = fmaxf(mx0, fmaxf(sacc[j][0], sacc[j][1]));
            mx1 = fmaxf(mx1, fmaxf(sacc[j][2], sacc[j][3]));
        }
        mx0 = fmaxf(mx0, __shfl_xor_sync(0xffffffffu, mx0, 1));
        mx0 = fmaxf(mx0, __shfl_xor_sync(0xffffffffu, mx0, 2));
        mx1 = fmaxf(mx1, __shfl_xor_sync(0xffffffffu, mx1, 1));
        mx1 = fmaxf(mx1, __shfl_xor_sync(0xffffffffu, mx1, 2));
        float nm0 = fmaxf(m0, mx0), nm1 = fmaxf(m1, mx1);
        float corr0 = fexp(m0 - nm0), corr1 = fexp(m1 - nm1);
        m0 = nm0; m1 = nm1;
        float s0 = 0.f, s1 = 0.f;
        // P fragments in registers: pfrag[c] is the A-operand for k-chunk c.
        uint32_t pfrag[4][4];
#pragma unroll
        for (int j = 0; j < 8; ++j) {
            float p00 = fexp(sacc[j][0] - m0);
            float p01 = fexp(sacc[j][1] - m0);
            float p10 = fexp(sacc[j][2] - m1);
            float p11 = fexp(sacc[j][3] - m1);
            s0 += p00 + p01; s1 += p10 + p11;
            __half2 hp0 = __halves2half2(__float2half(p00), __float2half(p01));
            __half2 hp1 = __halves2half2(__float2half(p10), __float2half(p11));
            const int c = j >> 1, hi = (j & 1) * 2;
            pfrag[c][hi + 0] = *(uint32_t*)&hp0;
            pfrag[c][hi + 1] = *(uint32_t*)&hp1;
        }
        s0 += __shfl_xor_sync(0xffffffffu, s0, 1);
        s0 += __shfl_xor_sync(0xffffffffu, s0, 2);
        s1 += __shfl_xor_sync(0xffffffffu, s1, 1);
        s1 += __shfl_xor_sync(0xffffffffu, s1, 2);
        l0 = l0 * corr0 + s0;
        l1 = l1 * corr1 + s1;
#pragma unroll
        for (int f = 0; f < 16; ++f) {
            o[f][0] *= corr0; o[f][1] *= corr0;
            o[f][2] *= corr1; o[f][3] *= corr1;
        }

        if (hasNext) { CPA_WAIT(1); } else { CPA_WAIT(0); }   // V(kt) done
        __syncthreads();

        // O += P @ V  (A from registers)
#pragma unroll
        for (int ks = 0; ks < 4; ++ks) {
#pragma unroll
            for (int p = 0; p < 4; ++p) {
                uint32_t vb[2][4];
#pragma unroll
                for (int u = 0; u < 2; ++u) {
                    uint32_t b0 = sbase + FOV + ((p * 2 + u) * 16 + rowB) * RSV + ks * 32 + colB;
                    LDSM4(vb[u], b0);
                }
#pragma unroll
                for (int u = 0; u < 2; ++u)
#pragma unroll
                    for (int half = 0; half < 2; ++half)
                        MMAF16(o[(p * 2 + u) * 2 + half], pfrag[ks], vb[u][half * 2], vb[u][half * 2 + 1]);
            }
        }
    }

    float i0 = 1.f / l0, i1 = 1.f / l1;
    int row0 = qt * 64 + warp_m * 16 + q4;
#pragma unroll
    for (int f = 0; f < 16; ++f) {
        int col = ocol0 + f * 8 + l4 * 2;
        *(__half2*)(cs + (size_t)row0 * D_MODEL + col) =
            __halves2half2(__float2half(o[f][0] * i0), __float2half(o[f][1] * i0));
        *(__half2*)(cs + (size_t)(row0 + 8) * D_MODEL + col) =
            __halves2half2(__float2half(o[f][2] * i1), __float2half(o[f][3] * i1));
    }
}

// ---------------------------------------------------------------------------
extern "C" void kernel_launch(void* const* d_in, const int* in_sizes, int n_in,
                              void* d_out, int out_size) {
    const float* x  = (const float*)d_in[0];
    const float* Wq = (const float*)d_in[1];
    const float* Wk = (const float*)d_in[2];
    const float* Wv = (const float*)d_in[3];
    const float* Wo = (const float*)d_in[4];
    float* out = (float*)d_out;

    __half *xs, *cs, *qs, *ks, *vt, *wq, *wk, *wv, *wo;
    float2* tab;
    cudaGetSymbolAddress((void**)&xs, g_xs);
    cudaGetSymbolAddress((void**)&cs, g_cs);
    cudaGetSymbolAddress((void**)&qs, g_Qs);
    cudaGetSymbolAddress((void**)&ks, g_Ks);
    cudaGetSymbolAddress((void**)&vt, g_Vt);
    cudaGetSymbolAddress((void**)&wq, g_WqT);
    cudaGetSymbolAddress((void**)&wk, g_WkT);
    cudaGetSymbolAddress((void**)&wv, g_WvT);
    cudaGetSymbolAddress((void**)&wo, g_WoT);
    cudaGetSymbolAddress((void**)&tab, g_rope);

    cudaFuncSetAttribute(hgemm_qkv, cudaFuncAttributeMaxDynamicSharedMemorySize, QKV_SMEM);
    cudaFuncSetAttribute(hgemm_o,   cudaFuncAttributeMaxDynamicSharedMemorySize, GSMEM);
    cudaFuncSetAttribute(flash_mma, cudaFuncAttributeMaxDynamicSharedMemorySize, FSMEM);

    prep_all<<<14848, 256>>>(x, Wq, Wk, Wv, Wo, xs, wq, wk, wv, wo, tab);
    hgemm_qkv<<<384, 256, QKV_SMEM>>>(xs, wq, wk, wv, qs, ks, vt, tab);
    flash_mma<<<dim3(N_TOK / 64, 16), 128, FSMEM>>>(qs, ks, vt, cs);
    hgemm_o<<<dim3(16, 16), 256, GSMEM>>>(cs, wo, out);

    (void)in_sizes; (void)n_in; (void)out_size;
}